// round 1
// baseline (speedup 1.0000x reference)
#include <cuda_runtime.h>
#include <math.h>

#define NMAX 50000
#define EMAX 800000
#define D 256
#define DIN 128

// ---------------- scratch (static device globals; no allocation) ----------------
__device__ float d_S[(size_t)NMAX * 1024];   // [N][4][256] type-separated neighbor sums
__device__ float d_hA[(size_t)NMAX * D];
__device__ float d_hB[(size_t)NMAX * D];
__device__ float d_agg[(size_t)NMAX * D];
__device__ float d_gi[(size_t)NMAX * 768];
__device__ float d_cnt[(size_t)NMAX * 4];    // per (node, etype) in-degree as float
__device__ float d_WT[(size_t)D * 1024];     // Wstack transposed: [256 out][1024 k]
__device__ float d_pooled[D];

// ---------------- helpers ----------------
__global__ void k_zero(float4* __restrict__ p, int n4) {
    int i = blockIdx.x * blockDim.x + threadIdx.x;
    if (i < n4) p[i] = make_float4(0.f, 0.f, 0.f, 0.f);
}

__global__ void k_counts(const int* __restrict__ dst, const int* __restrict__ typ,
                         float* __restrict__ cnt, int e) {
    int i = blockIdx.x * blockDim.x + threadIdx.x;
    if (i < e) atomicAdd(&cnt[(size_t)dst[i] * 4 + typ[i]], 1.0f);
}

// h0 = [features | zeros]  ([N,256])
__global__ void k_init_h(const float* __restrict__ f, float* __restrict__ h, int n) {
    int i = blockIdx.x * blockDim.x + threadIdx.x;
    int m = i >> 8, c = i & 255;
    if (m >= n) return;
    h[i] = (c < DIN) ? f[(size_t)m * DIN + c] : 0.f;
}

// WT[e][k] = Wstack[k][e], Wstack = W viewed as [1024,256]
__global__ void k_transpose(const float* __restrict__ W, float* __restrict__ WT) {
    int i = blockIdx.x * blockDim.x + threadIdx.x;
    if (i >= 256 * 1024) return;
    int e = i >> 10, k = i & 1023;
    WT[i] = W[(size_t)k * 256 + e];
}

// ---------------- edge scatter: S[dst][t][:] += h[src][:] ----------------
__device__ __forceinline__ void red_add_v4(float* p, float4 v) {
    asm volatile("red.global.add.v4.f32 [%0], {%1,%2,%3,%4};"
                 :: "l"(p), "f"(v.x), "f"(v.y), "f"(v.z), "f"(v.w) : "memory");
}

__global__ void k_scatter(const float* __restrict__ h, const int* __restrict__ src,
                          const int* __restrict__ dst, const int* __restrict__ typ,
                          float* __restrict__ S, int e) {
    long long i = (long long)blockIdx.x * blockDim.x + threadIdx.x;
    int ei = (int)(i >> 6);
    if (ei >= e) return;
    int c = ((int)i & 63) << 2;
    int s = __ldg(src + ei), d = __ldg(dst + ei), t = __ldg(typ + ei);
    float4 v = *reinterpret_cast<const float4*>(h + (size_t)s * D + c);
    float* p = S + ((size_t)d * 4 + t) * D + c;
    red_add_v4(p, v);
}

// ---------------- generic NT SGEMM: C[M,N] = A[M,K] * B[N,K]^T (+ epilogue) ----
// epi: 0 = none, 1 = +aux0[n], 2 = +sum_t cnt(aux0)[m,t]*b(aux1)[t,n]
#define BM 128
#define BN 128
#define BK 8
__global__ __launch_bounds__(256) void sgemm_nt(
    const float* __restrict__ A, const float* __restrict__ B, float* __restrict__ C,
    int M, int Nn, int K, int epi,
    const float* __restrict__ aux0, const float* __restrict__ aux1)
{
    __shared__ float As[2][BK][BM + 4];
    __shared__ float Bs[2][BK][BN + 4];
    const int tid = threadIdx.x;
    const int bm = blockIdx.y * BM;
    const int bn = blockIdx.x * BN;
    const int lr = tid >> 1;
    const int lk = (tid & 1) << 2;
    const float* Ap = A + (size_t)(bm + lr) * K + lk;
    const float* Bp = B + (size_t)(bn + lr) * K + lk;
    const bool aval = (bm + lr) < M;

    float4 a4 = aval ? __ldg((const float4*)Ap) : make_float4(0.f, 0.f, 0.f, 0.f);
    float4 b4 = __ldg((const float4*)Bp);
    As[0][lk + 0][lr] = a4.x; As[0][lk + 1][lr] = a4.y;
    As[0][lk + 2][lr] = a4.z; As[0][lk + 3][lr] = a4.w;
    Bs[0][lk + 0][lr] = b4.x; Bs[0][lk + 1][lr] = b4.y;
    Bs[0][lk + 2][lr] = b4.z; Bs[0][lk + 3][lr] = b4.w;
    __syncthreads();

    const int tx = tid & 15, ty = tid >> 4;
    float acc[8][8];
#pragma unroll
    for (int i = 0; i < 8; i++)
#pragma unroll
        for (int j = 0; j < 8; j++) acc[i][j] = 0.f;

    int buf = 0;
    for (int k0 = BK; k0 <= K; k0 += BK) {
        const bool more = (k0 < K);
        if (more) {
            a4 = aval ? __ldg((const float4*)(Ap + k0)) : make_float4(0.f, 0.f, 0.f, 0.f);
            b4 = __ldg((const float4*)(Bp + k0));
        }
#pragma unroll
        for (int kk = 0; kk < BK; kk++) {
            float af[8], bf[8];
#pragma unroll
            for (int i = 0; i < 8; i++) af[i] = As[buf][kk][ty * 8 + i];
#pragma unroll
            for (int j = 0; j < 8; j++) bf[j] = Bs[buf][kk][tx * 8 + j];
#pragma unroll
            for (int i = 0; i < 8; i++)
#pragma unroll
                for (int j = 0; j < 8; j++) acc[i][j] += af[i] * bf[j];
        }
        if (more) {
            buf ^= 1;
            As[buf][lk + 0][lr] = a4.x; As[buf][lk + 1][lr] = a4.y;
            As[buf][lk + 2][lr] = a4.z; As[buf][lk + 3][lr] = a4.w;
            Bs[buf][lk + 0][lr] = b4.x; Bs[buf][lk + 1][lr] = b4.y;
            Bs[buf][lk + 2][lr] = b4.z; Bs[buf][lk + 3][lr] = b4.w;
            __syncthreads();
        }
    }

    // epilogue
    float bias[8];
    float bt[4][8];
    if (epi == 1) {
#pragma unroll
        for (int j = 0; j < 8; j++) bias[j] = __ldg(aux0 + bn + tx * 8 + j);
    } else if (epi == 2) {
#pragma unroll
        for (int t = 0; t < 4; t++)
#pragma unroll
            for (int j = 0; j < 8; j++) bt[t][j] = __ldg(aux1 + t * 256 + bn + tx * 8 + j);
    }
#pragma unroll
    for (int i = 0; i < 8; i++) {
        int m = bm + ty * 8 + i;
        if (m >= M) continue;
        float add[8];
        if (epi == 1) {
#pragma unroll
            for (int j = 0; j < 8; j++) add[j] = bias[j];
        } else if (epi == 2) {
            float4 c4 = *reinterpret_cast<const float4*>(aux0 + (size_t)m * 4);
#pragma unroll
            for (int j = 0; j < 8; j++)
                add[j] = c4.x * bt[0][j] + c4.y * bt[1][j] + c4.z * bt[2][j] + c4.w * bt[3][j];
        } else {
#pragma unroll
            for (int j = 0; j < 8; j++) add[j] = 0.f;
        }
        float* Cp = C + (size_t)m * Nn + bn + tx * 8;
        float4 o0 = make_float4(acc[i][0] + add[0], acc[i][1] + add[1],
                                acc[i][2] + add[2], acc[i][3] + add[3]);
        float4 o1 = make_float4(acc[i][4] + add[4], acc[i][5] + add[5],
                                acc[i][6] + add[6], acc[i][7] + add[7]);
        *reinterpret_cast<float4*>(Cp) = o0;
        *reinterpret_cast<float4*>(Cp + 4) = o1;
    }
}

// ---------------- fused gh-GEMM + GRU update ----------------
// Block computes gh for all 3 gate panels (r,z,n) over a 128x64 tile of the
// 256-wide gate dim, then applies the GRU update in the epilogue.
__global__ __launch_bounds__(256) void k_gru(
    const float* __restrict__ hin, const float* __restrict__ Whh,
    const float* __restrict__ bhh, const float* __restrict__ gi,
    float* __restrict__ hout, int M)
{
    const int K = 256;
    __shared__ float As[2][16][128 + 4];
    __shared__ float Bs[2][3][16][64];
    const int tid = threadIdx.x;
    const int bm = blockIdx.y * 128;
    const int bn = blockIdx.x * 64;

    const int ar0 = tid >> 2;                 // rows 0..63
    const int ar1 = ar0 + 64;                 // rows 64..127
    const int ac = (tid & 3) << 2;            // k-col {0,4,8,12}
    const int br = tid >> 2;                  // B rows 0..63
    const float* Ap0 = hin + (size_t)(bm + ar0) * K + ac;
    const float* Ap1 = hin + (size_t)(bm + ar1) * K + ac;
    const bool av0 = (bm + ar0) < M, av1 = (bm + ar1) < M;
    const float* Bp0 = Whh + (size_t)(0 * 256 + bn + br) * K + ac;
    const float* Bp1 = Whh + (size_t)(1 * 256 + bn + br) * K + ac;
    const float* Bp2 = Whh + (size_t)(2 * 256 + bn + br) * K + ac;

    float4 a0 = av0 ? __ldg((const float4*)Ap0) : make_float4(0.f, 0.f, 0.f, 0.f);
    float4 a1 = av1 ? __ldg((const float4*)Ap1) : make_float4(0.f, 0.f, 0.f, 0.f);
    float4 b0 = __ldg((const float4*)Bp0);
    float4 b1 = __ldg((const float4*)Bp1);
    float4 b2 = __ldg((const float4*)Bp2);

#define STORE_TILE(BUF)                                                         \
    do {                                                                        \
        As[BUF][ac + 0][ar0] = a0.x; As[BUF][ac + 1][ar0] = a0.y;               \
        As[BUF][ac + 2][ar0] = a0.z; As[BUF][ac + 3][ar0] = a0.w;               \
        As[BUF][ac + 0][ar1] = a1.x; As[BUF][ac + 1][ar1] = a1.y;               \
        As[BUF][ac + 2][ar1] = a1.z; As[BUF][ac + 3][ar1] = a1.w;               \
        Bs[BUF][0][ac + 0][br] = b0.x; Bs[BUF][0][ac + 1][br] = b0.y;           \
        Bs[BUF][0][ac + 2][br] = b0.z; Bs[BUF][0][ac + 3][br] = b0.w;           \
        Bs[BUF][1][ac + 0][br] = b1.x; Bs[BUF][1][ac + 1][br] = b1.y;           \
        Bs[BUF][1][ac + 2][br] = b1.z; Bs[BUF][1][ac + 3][br] = b1.w;           \
        Bs[BUF][2][ac + 0][br] = b2.x; Bs[BUF][2][ac + 1][br] = b2.y;           \
        Bs[BUF][2][ac + 2][br] = b2.z; Bs[BUF][2][ac + 3][br] = b2.w;           \
    } while (0)

    STORE_TILE(0);
    __syncthreads();

    const int tx = tid & 15, ty = tid >> 4;
    float acc[3][8][4];
#pragma unroll
    for (int g = 0; g < 3; g++)
#pragma unroll
        for (int i = 0; i < 8; i++)
#pragma unroll
            for (int j = 0; j < 4; j++) acc[g][i][j] = 0.f;

    int buf = 0;
    for (int k0 = 16; k0 <= K; k0 += 16) {
        const bool more = (k0 < K);
        if (more) {
            a0 = av0 ? __ldg((const float4*)(Ap0 + k0)) : make_float4(0.f, 0.f, 0.f, 0.f);
            a1 = av1 ? __ldg((const float4*)(Ap1 + k0)) : make_float4(0.f, 0.f, 0.f, 0.f);
            b0 = __ldg((const float4*)(Bp0 + k0));
            b1 = __ldg((const float4*)(Bp1 + k0));
            b2 = __ldg((const float4*)(Bp2 + k0));
        }
#pragma unroll
        for (int kk = 0; kk < 16; kk++) {
            float af[8];
#pragma unroll
            for (int i = 0; i < 8; i++) af[i] = As[buf][kk][ty * 8 + i];
            float bf0[4], bf1[4], bf2[4];
#pragma unroll
            for (int j = 0; j < 4; j++) {
                bf0[j] = Bs[buf][0][kk][tx * 4 + j];
                bf1[j] = Bs[buf][1][kk][tx * 4 + j];
                bf2[j] = Bs[buf][2][kk][tx * 4 + j];
            }
#pragma unroll
            for (int i = 0; i < 8; i++)
#pragma unroll
                for (int j = 0; j < 4; j++) {
                    acc[0][i][j] += af[i] * bf0[j];
                    acc[1][i][j] += af[i] * bf1[j];
                    acc[2][i][j] += af[i] * bf2[j];
                }
        }
        if (more) {
            buf ^= 1;
            STORE_TILE(buf);
            __syncthreads();
        }
    }

    // GRU epilogue
#pragma unroll
    for (int i = 0; i < 8; i++) {
        int m = bm + ty * 8 + i;
        if (m >= M) continue;
        const float* gip = gi + (size_t)m * 768 + bn + tx * 4;
        float4 gir = *reinterpret_cast<const float4*>(gip);
        float4 giz = *reinterpret_cast<const float4*>(gip + 256);
        float4 gin = *reinterpret_cast<const float4*>(gip + 512);
        float4 hv = *reinterpret_cast<const float4*>(hin + (size_t)m * 256 + bn + tx * 4);
        float girx[4] = {gir.x, gir.y, gir.z, gir.w};
        float gizx[4] = {giz.x, giz.y, giz.z, giz.w};
        float ginx[4] = {gin.x, gin.y, gin.z, gin.w};
        float hvx[4] = {hv.x, hv.y, hv.z, hv.w};
        float ov[4];
#pragma unroll
        for (int j = 0; j < 4; j++) {
            int nc = bn + tx * 4 + j;
            float ghr = acc[0][i][j] + __ldg(bhh + nc);
            float ghz = acc[1][i][j] + __ldg(bhh + 256 + nc);
            float ghn = acc[2][i][j] + __ldg(bhh + 512 + nc);
            float r = 1.f / (1.f + expf(-(girx[j] + ghr)));
            float z = 1.f / (1.f + expf(-(gizx[j] + ghz)));
            float nn = tanhf(ginx[j] + r * ghn);
            ov[j] = (1.f - z) * nn + z * hvx[j];
        }
        *reinterpret_cast<float4*>(hout + (size_t)m * 256 + bn + tx * 4) =
            make_float4(ov[0], ov[1], ov[2], ov[3]);
    }
#undef STORE_TILE
}

// ---------------- pooling + classifier ----------------
__global__ void k_pool(const float* __restrict__ h, float* __restrict__ pooled, int M) {
    int c = threadIdx.x;           // 256 columns
    int r0 = blockIdx.x * 256;
    int rend = min(r0 + 256, M);
    float s = 0.f;
    for (int r = r0; r < rend; r++) s += h[(size_t)r * 256 + c];
    atomicAdd(&pooled[c], s);
}

__global__ void k_final(const float* __restrict__ pooled, const float* __restrict__ Wc,
                        const float* __restrict__ bc, float* __restrict__ out) {
    __shared__ float red[256];
    int t = threadIdx.x;
    red[t] = pooled[t] * Wc[t];
    __syncthreads();
    for (int s = 128; s > 0; s >>= 1) {
        if (t < s) red[t] += red[t + s];
        __syncthreads();
    }
    if (t == 0) out[0] = 1.f / (1.f + expf(-(red[0] + bc[0])));
}

// ---------------- launch ----------------
extern "C" void kernel_launch(void* const* d_in, const int* in_sizes, int n_in,
                              void* d_out, int out_size) {
    const float* features = (const float*)d_in[0];
    const int* esrc = (const int*)d_in[1];
    const int* edst = (const int*)d_in[2];
    const int* etyp = (const int*)d_in[3];
    const float* W   = (const float*)d_in[4];
    const float* b   = (const float*)d_in[5];
    const float* Wih = (const float*)d_in[6];
    const float* Whh = (const float*)d_in[7];
    const float* bih = (const float*)d_in[8];
    const float* bhh = (const float*)d_in[9];
    const float* Wc  = (const float*)d_in[10];
    const float* bc  = (const float*)d_in[11];
    float* out = (float*)d_out;

    const int M = in_sizes[0] / DIN;   // 50000
    const int E = in_sizes[1];         // 800000

    float *S, *hA, *hB, *agg, *gi, *cnt, *WT, *pooled;
    cudaGetSymbolAddress((void**)&S, d_S);
    cudaGetSymbolAddress((void**)&hA, d_hA);
    cudaGetSymbolAddress((void**)&hB, d_hB);
    cudaGetSymbolAddress((void**)&agg, d_agg);
    cudaGetSymbolAddress((void**)&gi, d_gi);
    cudaGetSymbolAddress((void**)&cnt, d_cnt);
    cudaGetSymbolAddress((void**)&WT, d_WT);
    cudaGetSymbolAddress((void**)&pooled, d_pooled);

    // one-time (per launch) setup
    k_zero<<<(M + 255) / 256, 256>>>((float4*)cnt, M);                 // M*4 floats = M float4
    k_counts<<<(E + 255) / 256, 256>>>(edst, etyp, cnt, E);
    k_init_h<<<((size_t)M * 256 + 255) / 256, 256>>>(features, hA, M);
    k_transpose<<<(256 * 1024 + 255) / 256, 256>>>(W, WT);

    float* hin = hA;
    float* hout = hB;
    const int mb = (M + 127) / 128;
    dim3 gAgg(2, mb), gGi(6, mb), gGru(4, mb);
    const int s4 = M * 1024 / 4;
    const long long scat_threads = (long long)E * 64;

    for (int step = 0; step < 8; step++) {
        k_zero<<<(s4 + 255) / 256, 256>>>((float4*)S, s4);
        k_scatter<<<(int)((scat_threads + 255) / 256), 256>>>(hin, esrc, edst, etyp, S, E);
        sgemm_nt<<<gAgg, 256>>>(S, WT, agg, M, 256, 1024, 2, cnt, b);
        sgemm_nt<<<gGi, 256>>>(agg, Wih, gi, M, 768, 256, 1, bih, nullptr);
        k_gru<<<gGru, 256>>>(hin, Whh, bhh, gi, hout, M);
        float* t = hin; hin = hout; hout = t;
    }

    k_zero<<<1, 64>>>((float4*)pooled, 64);
    k_pool<<<(M + 255) / 256, 256>>>(hin, pooled, M);
    k_final<<<1, 256>>>(pooled, Wc, bc, out);
}

// round 6
// speedup vs baseline: 1.6406x; 1.6406x over previous
#include <cuda_runtime.h>
#include <math.h>

#define NMAX 50000
#define EMAX 800000
#define D 256
#define DIN 128

// ---------------- scratch (static device globals; no allocation) ----------------
__device__ float d_S[(size_t)NMAX * 1024];   // [N][4][256] type-separated neighbor sums
__device__ float d_hA[(size_t)NMAX * D];
__device__ float d_hB[(size_t)NMAX * D];
__device__ float d_agg[(size_t)NMAX * D];
__device__ float d_gi[(size_t)NMAX * 768];
__device__ float d_cnt[(size_t)NMAX * 4];    // per (node, etype) in-degree as float
__device__ float d_WT[(size_t)D * 1024];     // Wstack transposed: [256 out][1024 k]
__device__ float d_pooled[D];

// ---------------- tf32 helpers ----------------
__device__ __forceinline__ unsigned f2tf32(float x) {
    unsigned r;
    asm("cvt.rna.tf32.f32 %0, %1;" : "=r"(r) : "f"(x));
    return r;
}

__device__ __forceinline__ void mma_tf32(float* d, const unsigned* a, const unsigned* b) {
    asm volatile(
        "mma.sync.aligned.m16n8k8.row.col.f32.tf32.tf32.f32 "
        "{%0,%1,%2,%3}, {%4,%5,%6,%7}, {%8,%9}, {%0,%1,%2,%3};\n"
        : "+f"(d[0]), "+f"(d[1]), "+f"(d[2]), "+f"(d[3])
        : "r"(a[0]), "r"(a[1]), "r"(a[2]), "r"(a[3]), "r"(b[0]), "r"(b[1]));
}

// ---------------- helpers ----------------
__global__ void k_zero(float4* __restrict__ p, int n4) {
    int i = blockIdx.x * blockDim.x + threadIdx.x;
    if (i < n4) p[i] = make_float4(0.f, 0.f, 0.f, 0.f);
}

__global__ void k_counts(const int* __restrict__ dst, const int* __restrict__ typ,
                         float* __restrict__ cnt, int e) {
    int i = blockIdx.x * blockDim.x + threadIdx.x;
    if (i < e) atomicAdd(&cnt[(size_t)dst[i] * 4 + typ[i]], 1.0f);
}

__global__ void k_init_h(const float* __restrict__ f, float* __restrict__ h, int n) {
    int i = blockIdx.x * blockDim.x + threadIdx.x;
    int m = i >> 8, c = i & 255;
    if (m >= n) return;
    h[i] = (c < DIN) ? f[(size_t)m * DIN + c] : 0.f;
}

__global__ void k_transpose(const float* __restrict__ W, float* __restrict__ WT) {
    int i = blockIdx.x * blockDim.x + threadIdx.x;
    if (i >= 256 * 1024) return;
    int e = i >> 10, k = i & 1023;
    WT[i] = W[(size_t)k * 256 + e];
}

// ---------------- edge scatter: S[dst][t][:] += h[src][:] ----------------
__device__ __forceinline__ void red_add_v4(float* p, float4 v) {
    asm volatile("red.global.add.v4.f32 [%0], {%1,%2,%3,%4};"
                 :: "l"(p), "f"(v.x), "f"(v.y), "f"(v.z), "f"(v.w) : "memory");
}

__global__ void k_scatter(const float* __restrict__ h, const int* __restrict__ src,
                          const int* __restrict__ dst, const int* __restrict__ typ,
                          float* __restrict__ S, int e) {
    long long i = (long long)blockIdx.x * blockDim.x + threadIdx.x;
    int ei = (int)(i >> 6);
    if (ei >= e) return;
    int c = ((int)i & 63) << 2;
    int s = __ldg(src + ei), d = __ldg(dst + ei), t = __ldg(typ + ei);
    float4 v = *reinterpret_cast<const float4*>(h + (size_t)s * D + c);
    float* p = S + ((size_t)d * 4 + t) * D + c;
    red_add_v4(p, v);
}

// ---------------- TF32 NT GEMM: C[M,N] = A[M,K] * B[N,K]^T (+ epilogue) ------
// epi: 0 = none, 1 = +aux0[n], 2 = +sum_t cnt(aux0)[m,t]*b(aux1)[t,n]
#define BM 128
#define BN 128
#define BK 16
__global__ __launch_bounds__(256) void sgemm_tf32(
    const float* __restrict__ A, const float* __restrict__ B, float* __restrict__ C,
    int M, int Nn, int K, int epi,
    const float* __restrict__ aux0, const float* __restrict__ aux1)
{
    __shared__ unsigned As[2][BK][BM + 8];   // stride 136 -> conflict-free frag loads
    __shared__ unsigned Bs[2][BK][BN + 8];
    const int tid = threadIdx.x;
    const int bm = blockIdx.y * BM;
    const int bn = blockIdx.x * BN;
    const int lr = tid >> 1;
    const int lk = (tid & 1) * 8;
    const float* Ap = A + (size_t)(bm + lr) * K + lk;
    const float* Bp = B + (size_t)(bn + lr) * K + lk;
    const bool aval = (bm + lr) < M;
    const float4 z4 = make_float4(0.f, 0.f, 0.f, 0.f);

    float4 a0, a1, b0, b1;
    a0 = aval ? __ldg((const float4*)Ap) : z4;
    a1 = aval ? __ldg((const float4*)(Ap + 4)) : z4;
    b0 = __ldg((const float4*)Bp);
    b1 = __ldg((const float4*)(Bp + 4));

#define ST_AB(BUF)                                                              \
    do {                                                                        \
        As[BUF][lk + 0][lr] = f2tf32(a0.x); As[BUF][lk + 1][lr] = f2tf32(a0.y); \
        As[BUF][lk + 2][lr] = f2tf32(a0.z); As[BUF][lk + 3][lr] = f2tf32(a0.w); \
        As[BUF][lk + 4][lr] = f2tf32(a1.x); As[BUF][lk + 5][lr] = f2tf32(a1.y); \
        As[BUF][lk + 6][lr] = f2tf32(a1.z); As[BUF][lk + 7][lr] = f2tf32(a1.w); \
        Bs[BUF][lk + 0][lr] = f2tf32(b0.x); Bs[BUF][lk + 1][lr] = f2tf32(b0.y); \
        Bs[BUF][lk + 2][lr] = f2tf32(b0.z); Bs[BUF][lk + 3][lr] = f2tf32(b0.w); \
        Bs[BUF][lk + 4][lr] = f2tf32(b1.x); Bs[BUF][lk + 5][lr] = f2tf32(b1.y); \
        Bs[BUF][lk + 6][lr] = f2tf32(b1.z); Bs[BUF][lk + 7][lr] = f2tf32(b1.w); \
    } while (0)

    ST_AB(0);
    __syncthreads();

    const int wid = tid >> 5, lane = tid & 31;
    const int wm = (wid & 1) * 64;        // 2 warps along M
    const int wn = (wid >> 1) * 32;       // 4 warps along N
    const int g = lane >> 2, tg = lane & 3;

    float acc[4][4][4];
#pragma unroll
    for (int i = 0; i < 4; i++)
#pragma unroll
        for (int j = 0; j < 4; j++)
#pragma unroll
            for (int q = 0; q < 4; q++) acc[i][j][q] = 0.f;

    int buf = 0;
    for (int k0 = BK; k0 <= K; k0 += BK) {
        const bool more = (k0 < K);
        if (more) {
            a0 = aval ? __ldg((const float4*)(Ap + k0)) : z4;
            a1 = aval ? __ldg((const float4*)(Ap + k0 + 4)) : z4;
            b0 = __ldg((const float4*)(Bp + k0));
            b1 = __ldg((const float4*)(Bp + k0 + 4));
        }
#pragma unroll
        for (int ks = 0; ks < BK; ks += 8) {
            unsigned af[4][4], bf[4][2];
#pragma unroll
            for (int mi = 0; mi < 4; mi++) {
                int m0 = wm + mi * 16 + g;
                af[mi][0] = As[buf][ks + tg][m0];
                af[mi][1] = As[buf][ks + tg][m0 + 8];
                af[mi][2] = As[buf][ks + tg + 4][m0];
                af[mi][3] = As[buf][ks + tg + 4][m0 + 8];
            }
#pragma unroll
            for (int nj = 0; nj < 4; nj++) {
                int n0 = wn + nj * 8 + g;
                bf[nj][0] = Bs[buf][ks + tg][n0];
                bf[nj][1] = Bs[buf][ks + tg + 4][n0];
            }
#pragma unroll
            for (int mi = 0; mi < 4; mi++)
#pragma unroll
                for (int nj = 0; nj < 4; nj++)
                    mma_tf32(acc[mi][nj], af[mi], bf[nj]);
        }
        if (more) {
            buf ^= 1;
            ST_AB(buf);
            __syncthreads();
        }
    }
#undef ST_AB

    // epilogue
#pragma unroll
    for (int mi = 0; mi < 4; mi++) {
#pragma unroll
        for (int rr = 0; rr < 2; rr++) {
            int m = bm + wm + mi * 16 + g + rr * 8;
            if (m >= M) continue;
            float4 c4 = make_float4(0.f, 0.f, 0.f, 0.f);
            if (epi == 2) c4 = *reinterpret_cast<const float4*>(aux0 + (size_t)m * 4);
            float* Cr = C + (size_t)m * Nn;
#pragma unroll
            for (int nj = 0; nj < 4; nj++) {
                int c = bn + wn + nj * 8 + 2 * tg;
                float add0 = 0.f, add1 = 0.f;
                if (epi == 1) {
                    add0 = __ldg(aux0 + c);
                    add1 = __ldg(aux0 + c + 1);
                } else if (epi == 2) {
                    add0 = c4.x * __ldg(aux1 + 0 * 256 + c) + c4.y * __ldg(aux1 + 1 * 256 + c)
                         + c4.z * __ldg(aux1 + 2 * 256 + c) + c4.w * __ldg(aux1 + 3 * 256 + c);
                    add1 = c4.x * __ldg(aux1 + 0 * 256 + c + 1) + c4.y * __ldg(aux1 + 1 * 256 + c + 1)
                         + c4.z * __ldg(aux1 + 2 * 256 + c + 1) + c4.w * __ldg(aux1 + 3 * 256 + c + 1);
                }
                float2 o = make_float2(acc[mi][nj][rr * 2 + 0] + add0,
                                       acc[mi][nj][rr * 2 + 1] + add1);
                *reinterpret_cast<float2*>(Cr + c) = o;
            }
        }
    }
}

// ---------------- TF32 fused gh-GEMM + GRU update ----------------
// gh[p] = hin @ Whh[p]^T over a 128x64 column tile, all 3 panels in one block,
// full GRU applied in the epilogue.
__global__ __launch_bounds__(256) void gru_tf32(
    const float* __restrict__ hin, const float* __restrict__ Whh,
    const float* __restrict__ bhh, const float* __restrict__ gi,
    float* __restrict__ hout, int M)
{
    __shared__ unsigned As[2][16][128 + 8];       // stride 136
    __shared__ unsigned Bs[2][3][16][64 + 8];     // stride 72
    const int tid = threadIdx.x;
    const int bm = blockIdx.y * 128;
    const int bn = blockIdx.x * 64;
    const int lr = tid >> 1;
    const int lk = (tid & 1) * 8;
    const float* Ap = hin + (size_t)(bm + lr) * 256 + lk;
    const bool aval = (bm + lr) < M;
    const bool bact = tid < 192;
    const int pan = (tid & 255) >> 6 == 3 ? 0 : tid >> 6;   // ((tid>>6)==3)?0:tid>>6
    const int rn = tid & 63;
    const float* Bp = Whh + (size_t)(pan * 256 + bn + rn) * 256;
    const float4 z4 = make_float4(0.f, 0.f, 0.f, 0.f);

    float4 a0, a1, q0, q1, q2, q3;
    a0 = aval ? __ldg((const float4*)Ap) : z4;
    a1 = aval ? __ldg((const float4*)(Ap + 4)) : z4;
    if (bact) {
        q0 = __ldg((const float4*)Bp);      q1 = __ldg((const float4*)(Bp + 4));
        q2 = __ldg((const float4*)(Bp + 8)); q3 = __ldg((const float4*)(Bp + 12));
    }

#define ST_G(BUF)                                                                \
    do {                                                                         \
        As[BUF][lk + 0][lr] = f2tf32(a0.x); As[BUF][lk + 1][lr] = f2tf32(a0.y);  \
        As[BUF][lk + 2][lr] = f2tf32(a0.z); As[BUF][lk + 3][lr] = f2tf32(a0.w);  \
        As[BUF][lk + 4][lr] = f2tf32(a1.x); As[BUF][lk + 5][lr] = f2tf32(a1.y);  \
        As[BUF][lk + 6][lr] = f2tf32(a1.z); As[BUF][lk + 7][lr] = f2tf32(a1.w);  \
        if (bact) {                                                              \
            Bs[BUF][pan][0][rn]  = f2tf32(q0.x); Bs[BUF][pan][1][rn]  = f2tf32(q0.y);  \
            Bs[BUF][pan][2][rn]  = f2tf32(q0.z); Bs[BUF][pan][3][rn]  = f2tf32(q0.w);  \
            Bs[BUF][pan][4][rn]  = f2tf32(q1.x); Bs[BUF][pan][5][rn]  = f2tf32(q1.y);  \
            Bs[BUF][pan][6][rn]  = f2tf32(q1.z); Bs[BUF][pan][7][rn]  = f2tf32(q1.w);  \
            Bs[BUF][pan][8][rn]  = f2tf32(q2.x); Bs[BUF][pan][9][rn]  = f2tf32(q2.y);  \
            Bs[BUF][pan][10][rn] = f2tf32(q2.z); Bs[BUF][pan][11][rn] = f2tf32(q2.w);  \
            Bs[BUF][pan][12][rn] = f2tf32(q3.x); Bs[BUF][pan][13][rn] = f2tf32(q3.y);  \
            Bs[BUF][pan][14][rn] = f2tf32(q3.z); Bs[BUF][pan][15][rn] = f2tf32(q3.w);  \
        }                                                                        \
    } while (0)

    ST_G(0);
    __syncthreads();

    const int wid = tid >> 5, lane = tid & 31;
    const int wm = (wid & 1) * 64;        // 2 warps along M (64 rows each)
    const int wn = (wid >> 1) * 16;       // 4 warps along N (16 cols each)
    const int g = lane >> 2, tg = lane & 3;

    float acc[3][4][2][4];
#pragma unroll
    for (int p = 0; p < 3; p++)
#pragma unroll
        for (int i = 0; i < 4; i++)
#pragma unroll
            for (int j = 0; j < 2; j++)
#pragma unroll
                for (int q = 0; q < 4; q++) acc[p][i][j][q] = 0.f;

    int buf = 0;
    for (int k0 = 16; k0 <= 256; k0 += 16) {
        const bool more = (k0 < 256);
        if (more) {
            a0 = aval ? __ldg((const float4*)(Ap + k0)) : z4;
            a1 = aval ? __ldg((const float4*)(Ap + k0 + 4)) : z4;
            if (bact) {
                q0 = __ldg((const float4*)(Bp + k0));      q1 = __ldg((const float4*)(Bp + k0 + 4));
                q2 = __ldg((const float4*)(Bp + k0 + 8));  q3 = __ldg((const float4*)(Bp + k0 + 12));
            }
        }
#pragma unroll
        for (int ks = 0; ks < 16; ks += 8) {
            unsigned af[4][4];
#pragma unroll
            for (int mi = 0; mi < 4; mi++) {
                int m0 = wm + mi * 16 + g;
                af[mi][0] = As[buf][ks + tg][m0];
                af[mi][1] = As[buf][ks + tg][m0 + 8];
                af[mi][2] = As[buf][ks + tg + 4][m0];
                af[mi][3] = As[buf][ks + tg + 4][m0 + 8];
            }
            unsigned bf[3][2][2];
#pragma unroll
            for (int p = 0; p < 3; p++)
#pragma unroll
                for (int nj = 0; nj < 2; nj++) {
                    int n0 = wn + nj * 8 + g;
                    bf[p][nj][0] = Bs[buf][p][ks + tg][n0];
                    bf[p][nj][1] = Bs[buf][p][ks + tg + 4][n0];
                }
#pragma unroll
            for (int p = 0; p < 3; p++)
#pragma unroll
                for (int mi = 0; mi < 4; mi++)
#pragma unroll
                    for (int nj = 0; nj < 2; nj++)
                        mma_tf32(acc[p][mi][nj], af[mi], bf[p][nj]);
        }
        if (more) {
            buf ^= 1;
            ST_G(buf);
            __syncthreads();
        }
    }
#undef ST_G

    // GRU epilogue
#pragma unroll
    for (int mi = 0; mi < 4; mi++) {
#pragma unroll
        for (int rr = 0; rr < 2; rr++) {
            int m = bm + wm + mi * 16 + g + rr * 8;
            if (m >= M) continue;
#pragma unroll
            for (int nj = 0; nj < 2; nj++) {
                int c = bn + wn + nj * 8 + 2 * tg;
                float2 gr = *reinterpret_cast<const float2*>(gi + (size_t)m * 768 + c);
                float2 gz = *reinterpret_cast<const float2*>(gi + (size_t)m * 768 + 256 + c);
                float2 gn = *reinterpret_cast<const float2*>(gi + (size_t)m * 768 + 512 + c);
                float2 hv = *reinterpret_cast<const float2*>(hin + (size_t)m * 256 + c);
                float2 br_ = *reinterpret_cast<const float2*>(bhh + c);
                float2 bz_ = *reinterpret_cast<const float2*>(bhh + 256 + c);
                float2 bn_ = *reinterpret_cast<const float2*>(bhh + 512 + c);
                float ghr0 = acc[0][mi][nj][rr * 2 + 0] + br_.x;
                float ghr1 = acc[0][mi][nj][rr * 2 + 1] + br_.y;
                float ghz0 = acc[1][mi][nj][rr * 2 + 0] + bz_.x;
                float ghz1 = acc[1][mi][nj][rr * 2 + 1] + bz_.y;
                float ghn0 = acc[2][mi][nj][rr * 2 + 0] + bn_.x;
                float ghn1 = acc[2][mi][nj][rr * 2 + 1] + bn_.y;
                float r0 = 1.f / (1.f + expf(-(gr.x + ghr0)));
                float r1 = 1.f / (1.f + expf(-(gr.y + ghr1)));
                float zz0 = 1.f / (1.f + expf(-(gz.x + ghz0)));
                float zz1 = 1.f / (1.f + expf(-(gz.y + ghz1)));
                float nn0 = tanhf(gn.x + r0 * ghn0);
                float nn1 = tanhf(gn.y + r1 * ghn1);
                float2 o = make_float2((1.f - zz0) * nn0 + zz0 * hv.x,
                                       (1.f - zz1) * nn1 + zz1 * hv.y);
                *reinterpret_cast<float2*>(hout + (size_t)m * 256 + c) = o;
            }
        }
    }
}

// ---------------- pooling + classifier ----------------
__global__ void k_pool(const float* __restrict__ h, float* __restrict__ pooled, int M) {
    int c = threadIdx.x;
    int r0 = blockIdx.x * 256;
    int rend = min(r0 + 256, M);
    float s = 0.f;
    for (int r = r0; r < rend; r++) s += h[(size_t)r * 256 + c];
    atomicAdd(&pooled[c], s);
}

__global__ void k_final(const float* __restrict__ pooled, const float* __restrict__ Wc,
                        const float* __restrict__ bc, float* __restrict__ out) {
    __shared__ float red[256];
    int t = threadIdx.x;
    red[t] = pooled[t] * Wc[t];
    __syncthreads();
    for (int s = 128; s > 0; s >>= 1) {
        if (t < s) red[t] += red[t + s];
        __syncthreads();
    }
    if (t == 0) out[0] = 1.f / (1.f + expf(-(red[0] + bc[0])));
}

// ---------------- launch ----------------
extern "C" void kernel_launch(void* const* d_in, const int* in_sizes, int n_in,
                              void* d_out, int out_size) {
    const float* features = (const float*)d_in[0];
    const int* esrc = (const int*)d_in[1];
    const int* edst = (const int*)d_in[2];
    const int* etyp = (const int*)d_in[3];
    const float* W   = (const float*)d_in[4];
    const float* b   = (const float*)d_in[5];
    const float* Wih = (const float*)d_in[6];
    const float* Whh = (const float*)d_in[7];
    const float* bih = (const float*)d_in[8];
    const float* bhh = (const float*)d_in[9];
    const float* Wc  = (const float*)d_in[10];
    const float* bc  = (const float*)d_in[11];
    float* out = (float*)d_out;

    const int M = in_sizes[0] / DIN;   // 50000
    const int E = in_sizes[1];         // 800000

    float *S, *hA, *hB, *agg, *gi, *cnt, *WT, *pooled;
    cudaGetSymbolAddress((void**)&S, d_S);
    cudaGetSymbolAddress((void**)&hA, d_hA);
    cudaGetSymbolAddress((void**)&hB, d_hB);
    cudaGetSymbolAddress((void**)&agg, d_agg);
    cudaGetSymbolAddress((void**)&gi, d_gi);
    cudaGetSymbolAddress((void**)&cnt, d_cnt);
    cudaGetSymbolAddress((void**)&WT, d_WT);
    cudaGetSymbolAddress((void**)&pooled, d_pooled);

    // one-time (per launch) setup
    k_zero<<<(M + 255) / 256, 256>>>((float4*)cnt, M);
    k_counts<<<(E + 255) / 256, 256>>>(edst, etyp, cnt, E);
    k_init_h<<<((size_t)M * 256 + 255) / 256, 256>>>(features, hA, M);
    k_transpose<<<(256 * 1024 + 255) / 256, 256>>>(W, WT);

    float* hin = hA;
    float* hout = hB;
    const int mb = (M + 127) / 128;
    dim3 gAgg(2, mb), gGi(6, mb), gGru(4, mb);
    const int s4 = M * 1024 / 4;
    const long long scat_threads = (long long)E * 64;

    for (int step = 0; step < 8; step++) {
        k_zero<<<(s4 + 255) / 256, 256>>>((float4*)S, s4);
        k_scatter<<<(int)((scat_threads + 255) / 256), 256>>>(hin, esrc, edst, etyp, S, E);
        sgemm_tf32<<<gAgg, 256>>>(S, WT, agg, M, 256, 1024, 2, cnt, b);
        sgemm_tf32<<<gGi, 256>>>(agg, Wih, gi, M, 768, 256, 1, bih, nullptr);
        gru_tf32<<<gGru, 256>>>(hin, Whh, bhh, gi, hout, M);
        float* t = hin; hin = hout; hout = t;
    }

    k_zero<<<1, 64>>>((float4*)pooled, 64);
    k_pool<<<(M + 255) / 256, 256>>>(hin, pooled, M);
    k_final<<<1, 256>>>(pooled, Wc, bc, out);
}

// round 11
// speedup vs baseline: 2.5178x; 1.5347x over previous
#include <cuda_runtime.h>
#include <cuda_bf16.h>
#include <math.h>

#define NMAX 50000
#define EMAX 800000
#define D 256
#define DIN 128

// ---------------- scratch (static device globals; no allocation) ----------------
__device__ unsigned d_Sw[(size_t)NMAX * 512];   // [N*4 pairs][128 words] bf16x2 neighbor sums
__device__ float d_hA[(size_t)NMAX * D];
__device__ float d_hB[(size_t)NMAX * D];
__device__ float d_agg[(size_t)NMAX * D];
__device__ float d_gi[(size_t)NMAX * 768];
__device__ float d_cnt[(size_t)NMAX * 4];       // per (node,etype) in-degree (float, for epilogue)
__device__ float d_WT[(size_t)D * 1024];        // Wstack transposed: [256 out][1024 k]
__device__ float d_pooled[D];
// CSR build
__device__ int d_icnt[(size_t)NMAX * 4];
__device__ int d_cur[(size_t)NMAX * 4];
__device__ int d_off[(size_t)NMAX * 4 + 1];
__device__ int d_bsum[256];
__device__ int d_ss[EMAX];                       // src ids sorted by (dst,type)

// ---------------- bf16 helpers ----------------
// pack (lo, hi) -> bf16x2 word, lo in low 16 bits
__device__ __forceinline__ unsigned pk(float lo, float hi) {
    __nv_bfloat162 t = __floats2bfloat162_rn(lo, hi);
    return *reinterpret_cast<unsigned*>(&t);
}

__device__ __forceinline__ void mma_bf16(float* d, const unsigned* a, const unsigned* b) {
    asm volatile(
        "mma.sync.aligned.m16n8k16.row.col.f32.bf16.bf16.f32 "
        "{%0,%1,%2,%3}, {%4,%5,%6,%7}, {%8,%9}, {%0,%1,%2,%3};\n"
        : "+f"(d[0]), "+f"(d[1]), "+f"(d[2]), "+f"(d[3])
        : "r"(a[0]), "r"(a[1]), "r"(a[2]), "r"(a[3]), "r"(b[0]), "r"(b[1]));
}

// ---------------- helpers ----------------
__global__ void k_zero(float4* __restrict__ p, int n4) {
    int i = blockIdx.x * blockDim.x + threadIdx.x;
    if (i < n4) p[i] = make_float4(0.f, 0.f, 0.f, 0.f);
}

__global__ void k_count_int(const int* __restrict__ dst, const int* __restrict__ typ,
                            int* __restrict__ icnt, int e) {
    int i = blockIdx.x * blockDim.x + threadIdx.x;
    if (i < e) atomicAdd(&icnt[(size_t)dst[i] * 4 + typ[i]], 1);
}

__global__ void k_cnt2float(const int* __restrict__ icnt, float* __restrict__ cnt, int np) {
    int i = blockIdx.x * blockDim.x + threadIdx.x;
    if (i < np) cnt[i] = (float)icnt[i];
}

// exclusive scan, 1024 elems per block
__global__ void k_scan1(const int* __restrict__ in, int* __restrict__ out,
                        int* __restrict__ bsum, int np) {
    __shared__ int sh[256];
    int t = threadIdx.x;
    int base = blockIdx.x * 1024 + t * 4;
    int v0 = (base + 0 < np) ? in[base + 0] : 0;
    int v1 = (base + 1 < np) ? in[base + 1] : 0;
    int v2 = (base + 2 < np) ? in[base + 2] : 0;
    int v3 = (base + 3 < np) ? in[base + 3] : 0;
    int s = v0 + v1 + v2 + v3;
    sh[t] = s;
    __syncthreads();
    for (int ofs = 1; ofs < 256; ofs <<= 1) {
        int x = (t >= ofs) ? sh[t - ofs] : 0;
        __syncthreads();
        sh[t] += x;
        __syncthreads();
    }
    int ex = sh[t] - s;
    if (base + 0 < np) out[base + 0] = ex;
    if (base + 1 < np) out[base + 1] = ex + v0;
    if (base + 2 < np) out[base + 2] = ex + v0 + v1;
    if (base + 3 < np) out[base + 3] = ex + v0 + v1 + v2;
    if (t == 255) bsum[blockIdx.x] = sh[255];
}

__global__ void k_scan2(int* __restrict__ bsum, int nb) {
    __shared__ int sh[256];
    int t = threadIdx.x;
    int v = (t < nb) ? bsum[t] : 0;
    sh[t] = v;
    __syncthreads();
    for (int ofs = 1; ofs < 256; ofs <<= 1) {
        int x = (t >= ofs) ? sh[t - ofs] : 0;
        __syncthreads();
        sh[t] += x;
        __syncthreads();
    }
    if (t < nb) bsum[t] = sh[t] - v;   // exclusive
}

__global__ void k_scan3(int* __restrict__ off, const int* __restrict__ bsum,
                        int np, int total) {
    int add = bsum[blockIdx.x];
    int base = blockIdx.x * 1024 + threadIdx.x * 4;
#pragma unroll
    for (int j = 0; j < 4; j++)
        if (base + j < np) off[base + j] += add;
    if (blockIdx.x == 0 && threadIdx.x == 0) off[np] = total;
}

__global__ void k_place(const int* __restrict__ src, const int* __restrict__ dst,
                        const int* __restrict__ typ, const int* __restrict__ off,
                        int* __restrict__ cur, int* __restrict__ ss, int e) {
    int i = blockIdx.x * blockDim.x + threadIdx.x;
    if (i >= e) return;
    int p = dst[i] * 4 + typ[i];
    int pos = off[p] + atomicAdd(&cur[p], 1);
    ss[pos] = src[i];
}

// h0 = [features | zeros]
__global__ void k_init_h(const float* __restrict__ f, float* __restrict__ h, int n) {
    int i = blockIdx.x * blockDim.x + threadIdx.x;
    int m = i >> 8, c = i & 255;
    if (m >= n) return;
    h[i] = (c < DIN) ? f[(size_t)m * DIN + c] : 0.f;
}

__global__ void k_transpose(const float* __restrict__ W, float* __restrict__ WT) {
    int i = blockIdx.x * blockDim.x + threadIdx.x;
    if (i >= 256 * 1024) return;
    int e = i >> 10, k = i & 1023;
    WT[i] = W[(size_t)k * 256 + e];
}

// ---------------- CSR gather: Sw[p][:] = bf16( sum_{e in bucket p} h[src[e]][:] ) ----
__global__ void k_gather(const float* __restrict__ h, const int* __restrict__ ss,
                         const int* __restrict__ off, unsigned* __restrict__ Sw, int np) {
    int p = blockIdx.x * 8 + (threadIdx.x >> 5);
    if (p >= np) return;
    int lane = threadIdx.x & 31;
    int beg = __ldg(off + p), end = __ldg(off + p + 1);
    float a0 = 0.f, a1 = 0.f, a2 = 0.f, a3 = 0.f, a4 = 0.f, a5 = 0.f, a6 = 0.f, a7 = 0.f;
    const int cb = lane * 8;
    for (int e = beg; e < end; e++) {
        const float4* hp = (const float4*)(h + (size_t)__ldg(ss + e) * D + cb);
        float4 u = __ldg(hp);
        float4 v = __ldg(hp + 1);
        a0 += u.x; a1 += u.y; a2 += u.z; a3 += u.w;
        a4 += v.x; a5 += v.y; a6 += v.z; a7 += v.w;
    }
    uint4 o;
    o.x = pk(a0, a1); o.y = pk(a2, a3); o.z = pk(a4, a5); o.w = pk(a6, a7);
    *reinterpret_cast<uint4*>(Sw + (size_t)p * 128 + lane * 4) = o;
}

// ---------------- BF16 NT GEMM: C[M,N] = A[M,K] * B[N,K]^T (+ epilogue) ------
// ABF: A is pre-packed bf16x2 words; else fp32 converted on staging.
// epi: 0 none, 1 +aux0[n], 2 +sum_t cnt(aux0)[m,t]*b(aux1)[t,n]
#define BM 128
#define BN 128
#define BK 16
template <bool ABF>
__global__ __launch_bounds__(256) void gemm_bf16(
    const void* __restrict__ Av, const float* __restrict__ B, float* __restrict__ C,
    int M, int Nn, int K, int epi,
    const float* __restrict__ aux0, const float* __restrict__ aux1)
{
    __shared__ unsigned As[2][8][BM + 8];
    __shared__ unsigned Bs[2][8][BN + 8];
    const int tid = threadIdx.x;
    const int bm = blockIdx.y * BM;
    const int bn = blockIdx.x * BN;
    const int lr = tid >> 1;
    const int lh = tid & 1;           // half: k 0-7 or 8-15 (4 words)
    const bool aval = (bm + lr) < M;
    const float4 z4 = make_float4(0.f, 0.f, 0.f, 0.f);
    const uint4 zu = make_uint4(0u, 0u, 0u, 0u);

    const unsigned* Awp = (const unsigned*)Av + (size_t)(bm + lr) * (K >> 1) + lh * 4;
    const float* Afp = (const float*)Av + (size_t)(bm + lr) * K + lh * 8;
    const float* Bp = B + (size_t)(bn + lr) * K + lh * 8;

    uint4 aw; float4 a0, a1, b0, b1;
    if (ABF) {
        aw = aval ? __ldg((const uint4*)Awp) : zu;
    } else {
        a0 = aval ? __ldg((const float4*)Afp) : z4;
        a1 = aval ? __ldg((const float4*)(Afp + 4)) : z4;
    }
    b0 = __ldg((const float4*)Bp);
    b1 = __ldg((const float4*)(Bp + 4));

#define ST_AB(BUF)                                                                \
    do {                                                                          \
        if (ABF) {                                                                \
            As[BUF][lh * 4 + 0][lr] = aw.x; As[BUF][lh * 4 + 1][lr] = aw.y;       \
            As[BUF][lh * 4 + 2][lr] = aw.z; As[BUF][lh * 4 + 3][lr] = aw.w;       \
        } else {                                                                  \
            As[BUF][lh * 4 + 0][lr] = pk(a0.x, a0.y);                             \
            As[BUF][lh * 4 + 1][lr] = pk(a0.z, a0.w);                             \
            As[BUF][lh * 4 + 2][lr] = pk(a1.x, a1.y);                             \
            As[BUF][lh * 4 + 3][lr] = pk(a1.z, a1.w);                             \
        }                                                                         \
        Bs[BUF][lh * 4 + 0][lr] = pk(b0.x, b0.y);                                 \
        Bs[BUF][lh * 4 + 1][lr] = pk(b0.z, b0.w);                                 \
        Bs[BUF][lh * 4 + 2][lr] = pk(b1.x, b1.y);                                 \
        Bs[BUF][lh * 4 + 3][lr] = pk(b1.z, b1.w);                                 \
    } while (0)

    ST_AB(0);
    __syncthreads();

    const int wid = tid >> 5, lane = tid & 31;
    const int wm = (wid & 1) * 64;        // 2 warps along M
    const int wn = (wid >> 1) * 32;       // 4 warps along N
    const int g = lane >> 2, tg = lane & 3;

    float acc[4][4][4];
#pragma unroll
    for (int i = 0; i < 4; i++)
#pragma unroll
        for (int j = 0; j < 4; j++)
#pragma unroll
            for (int q = 0; q < 4; q++) acc[i][j][q] = 0.f;

    int buf = 0;
    for (int k0 = BK; k0 <= K; k0 += BK) {
        const bool more = (k0 < K);
        if (more) {
            if (ABF) {
                aw = aval ? __ldg((const uint4*)(Awp + (k0 >> 1))) : zu;
            } else {
                a0 = aval ? __ldg((const float4*)(Afp + k0)) : z4;
                a1 = aval ? __ldg((const float4*)(Afp + k0 + 4)) : z4;
            }
            b0 = __ldg((const float4*)(Bp + k0));
            b1 = __ldg((const float4*)(Bp + k0 + 4));
        }
        {
            unsigned af[4][4], bfr[4][2];
#pragma unroll
            for (int mi = 0; mi < 4; mi++) {
                int m0 = wm + mi * 16 + g;
                af[mi][0] = As[buf][tg][m0];
                af[mi][1] = As[buf][tg][m0 + 8];
                af[mi][2] = As[buf][tg + 4][m0];
                af[mi][3] = As[buf][tg + 4][m0 + 8];
            }
#pragma unroll
            for (int nj = 0; nj < 4; nj++) {
                int n0 = wn + nj * 8 + g;
                bfr[nj][0] = Bs[buf][tg][n0];
                bfr[nj][1] = Bs[buf][tg + 4][n0];
            }
#pragma unroll
            for (int mi = 0; mi < 4; mi++)
#pragma unroll
                for (int nj = 0; nj < 4; nj++)
                    mma_bf16(acc[mi][nj], af[mi], bfr[nj]);
        }
        if (more) {
            buf ^= 1;
            ST_AB(buf);
            __syncthreads();
        }
    }
#undef ST_AB

    // epilogue
#pragma unroll
    for (int mi = 0; mi < 4; mi++) {
#pragma unroll
        for (int rr = 0; rr < 2; rr++) {
            int m = bm + wm + mi * 16 + g + rr * 8;
            if (m >= M) continue;
            float4 c4 = make_float4(0.f, 0.f, 0.f, 0.f);
            if (epi == 2) c4 = *reinterpret_cast<const float4*>(aux0 + (size_t)m * 4);
            float* Cr = C + (size_t)m * Nn;
#pragma unroll
            for (int nj = 0; nj < 4; nj++) {
                int c = bn + wn + nj * 8 + 2 * tg;
                float add0 = 0.f, add1 = 0.f;
                if (epi == 1) {
                    add0 = __ldg(aux0 + c);
                    add1 = __ldg(aux0 + c + 1);
                } else if (epi == 2) {
                    add0 = c4.x * __ldg(aux1 + 0 * 256 + c) + c4.y * __ldg(aux1 + 1 * 256 + c)
                         + c4.z * __ldg(aux1 + 2 * 256 + c) + c4.w * __ldg(aux1 + 3 * 256 + c);
                    add1 = c4.x * __ldg(aux1 + 0 * 256 + c + 1) + c4.y * __ldg(aux1 + 1 * 256 + c + 1)
                         + c4.z * __ldg(aux1 + 2 * 256 + c + 1) + c4.w * __ldg(aux1 + 3 * 256 + c + 1);
                }
                float2 o = make_float2(acc[mi][nj][rr * 2 + 0] + add0,
                                       acc[mi][nj][rr * 2 + 1] + add1);
                *reinterpret_cast<float2*>(Cr + c) = o;
            }
        }
    }
}

// ---------------- BF16 fused gh-GEMM + GRU update ----------------
__global__ __launch_bounds__(256) void gru_bf16(
    const float* __restrict__ hin, const float* __restrict__ Whh,
    const float* __restrict__ bhh, const float* __restrict__ gi,
    float* __restrict__ hout, int M)
{
    __shared__ unsigned As[2][8][128 + 8];
    __shared__ unsigned Bs[2][3][8][64 + 8];
    const int tid = threadIdx.x;
    const int bm = blockIdx.y * 128;
    const int bn = blockIdx.x * 64;
    const int lr = tid >> 1;
    const int lh = tid & 1;
    const float* Ap = hin + (size_t)(bm + lr) * 256 + lh * 8;
    const bool aval = (bm + lr) < M;
    const bool bact = tid < 192;
    const int pan = (tid >> 6) == 3 ? 0 : (tid >> 6);
    const int rn = tid & 63;
    const float* Bp = Whh + (size_t)(pan * 256 + bn + rn) * 256;
    const float4 z4 = make_float4(0.f, 0.f, 0.f, 0.f);

    float4 a0, a1;
    float4 q0 = z4, q1 = z4, q2 = z4, q3 = z4;
    a0 = aval ? __ldg((const float4*)Ap) : z4;
    a1 = aval ? __ldg((const float4*)(Ap + 4)) : z4;
    if (bact) {
        q0 = __ldg((const float4*)Bp);       q1 = __ldg((const float4*)(Bp + 4));
        q2 = __ldg((const float4*)(Bp + 8)); q3 = __ldg((const float4*)(Bp + 12));
    }

#define ST_G(BUF)                                                                 \
    do {                                                                          \
        As[BUF][lh * 4 + 0][lr] = pk(a0.x, a0.y);                                 \
        As[BUF][lh * 4 + 1][lr] = pk(a0.z, a0.w);                                 \
        As[BUF][lh * 4 + 2][lr] = pk(a1.x, a1.y);                                 \
        As[BUF][lh * 4 + 3][lr] = pk(a1.z, a1.w);                                 \
        if (bact) {                                                               \
            Bs[BUF][pan][0][rn] = pk(q0.x, q0.y); Bs[BUF][pan][1][rn] = pk(q0.z, q0.w); \
            Bs[BUF][pan][2][rn] = pk(q1.x, q1.y); Bs[BUF][pan][3][rn] = pk(q1.z, q1.w); \
            Bs[BUF][pan][4][rn] = pk(q2.x, q2.y); Bs[BUF][pan][5][rn] = pk(q2.z, q2.w); \
            Bs[BUF][pan][6][rn] = pk(q3.x, q3.y); Bs[BUF][pan][7][rn] = pk(q3.z, q3.w); \
        }                                                                         \
    } while (0)

    ST_G(0);
    __syncthreads();

    const int wid = tid >> 5, lane = tid & 31;
    const int wm = (wid & 1) * 64;
    const int wn = (wid >> 1) * 16;
    const int g = lane >> 2, tg = lane & 3;

    float acc[3][4][2][4];
#pragma unroll
    for (int p = 0; p < 3; p++)
#pragma unroll
        for (int i = 0; i < 4; i++)
#pragma unroll
            for (int j = 0; j < 2; j++)
#pragma unroll
                for (int q = 0; q < 4; q++) acc[p][i][j][q] = 0.f;

    int buf = 0;
    for (int k0 = 16; k0 <= 256; k0 += 16) {
        const bool more = (k0 < 256);
        if (more) {
            a0 = aval ? __ldg((const float4*)(Ap + k0)) : z4;
            a1 = aval ? __ldg((const float4*)(Ap + k0 + 4)) : z4;
            if (bact) {
                q0 = __ldg((const float4*)(Bp + k0));      q1 = __ldg((const float4*)(Bp + k0 + 4));
                q2 = __ldg((const float4*)(Bp + k0 + 8));  q3 = __ldg((const float4*)(Bp + k0 + 12));
            }
        }
        {
            unsigned af[4][4];
#pragma unroll
            for (int mi = 0; mi < 4; mi++) {
                int m0 = wm + mi * 16 + g;
                af[mi][0] = As[buf][tg][m0];
                af[mi][1] = As[buf][tg][m0 + 8];
                af[mi][2] = As[buf][tg + 4][m0];
                af[mi][3] = As[buf][tg + 4][m0 + 8];
            }
            unsigned bfr[3][2][2];
#pragma unroll
            for (int p = 0; p < 3; p++)
#pragma unroll
                for (int nj = 0; nj < 2; nj++) {
                    int n0 = wn + nj * 8 + g;
                    bfr[p][nj][0] = Bs[buf][p][tg][n0];
                    bfr[p][nj][1] = Bs[buf][p][tg + 4][n0];
                }
#pragma unroll
            for (int p = 0; p < 3; p++)
#pragma unroll
                for (int mi = 0; mi < 4; mi++)
#pragma unroll
                    for (int nj = 0; nj < 2; nj++)
                        mma_bf16(acc[p][mi][nj], af[mi], bfr[p][nj]);
        }
        if (more) {
            buf ^= 1;
            ST_G(buf);
            __syncthreads();
        }
    }
#undef ST_G

    // GRU epilogue
#pragma unroll
    for (int mi = 0; mi < 4; mi++) {
#pragma unroll
        for (int rr = 0; rr < 2; rr++) {
            int m = bm + wm + mi * 16 + g + rr * 8;
            if (m >= M) continue;
#pragma unroll
            for (int nj = 0; nj < 2; nj++) {
                int c = bn + wn + nj * 8 + 2 * tg;
                float2 gr = *reinterpret_cast<const float2*>(gi + (size_t)m * 768 + c);
                float2 gz = *reinterpret_cast<const float2*>(gi + (size_t)m * 768 + 256 + c);
                float2 gn = *reinterpret_cast<const float2*>(gi + (size_t)m * 768 + 512 + c);
                float2 hv = *reinterpret_cast<const float2*>(hin + (size_t)m * 256 + c);
                float2 br_ = *reinterpret_cast<const float2*>(bhh + c);
                float2 bz_ = *reinterpret_cast<const float2*>(bhh + 256 + c);
                float2 bn_ = *reinterpret_cast<const float2*>(bhh + 512 + c);
                float ghr0 = acc[0][mi][nj][rr * 2 + 0] + br_.x;
                float ghr1 = acc[0][mi][nj][rr * 2 + 1] + br_.y;
                float ghz0 = acc[1][mi][nj][rr * 2 + 0] + bz_.x;
                float ghz1 = acc[1][mi][nj][rr * 2 + 1] + bz_.y;
                float ghn0 = acc[2][mi][nj][rr * 2 + 0] + bn_.x;
                float ghn1 = acc[2][mi][nj][rr * 2 + 1] + bn_.y;
                float r0 = 1.f / (1.f + expf(-(gr.x + ghr0)));
                float r1 = 1.f / (1.f + expf(-(gr.y + ghr1)));
                float zz0 = 1.f / (1.f + expf(-(gz.x + ghz0)));
                float zz1 = 1.f / (1.f + expf(-(gz.y + ghz1)));
                float nn0 = tanhf(gn.x + r0 * ghn0);
                float nn1 = tanhf(gn.y + r1 * ghn1);
                float2 o = make_float2((1.f - zz0) * nn0 + zz0 * hv.x,
                                       (1.f - zz1) * nn1 + zz1 * hv.y);
                *reinterpret_cast<float2*>(hout + (size_t)m * 256 + c) = o;
            }
        }
    }
}

// ---------------- pooling + classifier ----------------
__global__ void k_pool(const float* __restrict__ h, float* __restrict__ pooled, int M) {
    int c = threadIdx.x;
    int r0 = blockIdx.x * 256;
    int rend = min(r0 + 256, M);
    float s = 0.f;
    for (int r = r0; r < rend; r++) s += h[(size_t)r * 256 + c];
    atomicAdd(&pooled[c], s);
}

__global__ void k_final(const float* __restrict__ pooled, const float* __restrict__ Wc,
                        const float* __restrict__ bc, float* __restrict__ out) {
    __shared__ float red[256];
    int t = threadIdx.x;
    red[t] = pooled[t] * Wc[t];
    __syncthreads();
    for (int s = 128; s > 0; s >>= 1) {
        if (t < s) red[t] += red[t + s];
        __syncthreads();
    }
    if (t == 0) out[0] = 1.f / (1.f + expf(-(red[0] + bc[0])));
}

// ---------------- launch ----------------
extern "C" void kernel_launch(void* const* d_in, const int* in_sizes, int n_in,
                              void* d_out, int out_size) {
    const float* features = (const float*)d_in[0];
    const int* esrc = (const int*)d_in[1];
    const int* edst = (const int*)d_in[2];
    const int* etyp = (const int*)d_in[3];
    const float* W   = (const float*)d_in[4];
    const float* b   = (const float*)d_in[5];
    const float* Wih = (const float*)d_in[6];
    const float* Whh = (const float*)d_in[7];
    const float* bih = (const float*)d_in[8];
    const float* bhh = (const float*)d_in[9];
    const float* Wc  = (const float*)d_in[10];
    const float* bc  = (const float*)d_in[11];
    float* out = (float*)d_out;

    const int M = in_sizes[0] / DIN;   // 50000
    const int E = in_sizes[1];         // 800000
    const int np = M * 4;              // 200000 (dst,type) buckets

    unsigned* Sw;
    float *hA, *hB, *agg, *gi, *cnt, *WT, *pooled;
    int *icnt, *cur, *off, *bsum, *ss;
    cudaGetSymbolAddress((void**)&Sw, d_Sw);
    cudaGetSymbolAddress((void**)&hA, d_hA);
    cudaGetSymbolAddress((void**)&hB, d_hB);
    cudaGetSymbolAddress((void**)&agg, d_agg);
    cudaGetSymbolAddress((void**)&gi, d_gi);
    cudaGetSymbolAddress((void**)&cnt, d_cnt);
    cudaGetSymbolAddress((void**)&WT, d_WT);
    cudaGetSymbolAddress((void**)&pooled, d_pooled);
    cudaGetSymbolAddress((void**)&icnt, d_icnt);
    cudaGetSymbolAddress((void**)&cur, d_cur);
    cudaGetSymbolAddress((void**)&off, d_off);
    cudaGetSymbolAddress((void**)&bsum, d_bsum);
    cudaGetSymbolAddress((void**)&ss, d_ss);

    // ---- one-time (per launch) setup: CSR build + h0 + WT ----
    const int nb = (np + 1023) / 1024;
    k_zero<<<(np / 4 + 255) / 256, 256>>>((float4*)icnt, np / 4);
    k_zero<<<(np / 4 + 255) / 256, 256>>>((float4*)cur, np / 4);
    k_count_int<<<(E + 255) / 256, 256>>>(edst, etyp, icnt, E);
    k_cnt2float<<<(np + 255) / 256, 256>>>(icnt, cnt, np);
    k_scan1<<<nb, 256>>>(icnt, off, bsum, np);
    k_scan2<<<1, 256>>>(bsum, nb);
    k_scan3<<<nb, 256>>>(off, bsum, np, E);
    k_place<<<(E + 255) / 256, 256>>>(esrc, edst, etyp, off, cur, ss, E);
    k_init_h<<<((size_t)M * 256 + 255) / 256, 256>>>(features, hA, M);
    k_transpose<<<(256 * 1024 + 255) / 256, 256>>>(W, WT);

    float* hin = hA;
    float* hout = hB;
    const int mb = (M + 127) / 128;
    dim3 gAgg(2, mb), gGi(6, mb), gGru(4, mb);
    const int gGather = (np + 7) / 8;

    for (int step = 0; step < 8; step++) {
        k_gather<<<gGather, 256>>>(hin, ss, off, Sw, np);
        gemm_bf16<true><<<gAgg, 256>>>(Sw, WT, agg, M, 256, 1024, 2, cnt, b);
        gemm_bf16<false><<<gGi, 256>>>(agg, Wih, gi, M, 768, 256, 1, bih, nullptr);
        gru_bf16<<<gGru, 256>>>(hin, Whh, bhh, gi, hout, M);
        float* t = hin; hin = hout; hout = t;
    }

    k_zero<<<1, 64>>>((float4*)pooled, 64);
    k_pool<<<(M + 255) / 256, 256>>>(hin, pooled, M);
    k_final<<<1, 256>>>(pooled, Wc, bc, out);
}

// round 12
// speedup vs baseline: 2.9792x; 1.1833x over previous
#include <cuda_runtime.h>
#include <cuda_bf16.h>
#include <math.h>

#define NMAX 50000
#define EMAX 800000
#define D 256
#define DIN 128

// ---------------- scratch (static device globals; no allocation) ----------------
__device__ unsigned d_Sw[(size_t)NMAX * 512];    // [N*4 buckets][128 words] bf16x2 neighbor sums
__device__ float d_hA[(size_t)NMAX * D];         // fp32 h (ping)
__device__ float d_hB[(size_t)NMAX * D];         // fp32 h (pong)
__device__ unsigned d_hbfA[(size_t)NMAX * 128];  // bf16x2 packed h (ping)
__device__ unsigned d_hbfB[(size_t)NMAX * 128];  // bf16x2 packed h (pong)
__device__ unsigned d_aggw[(size_t)NMAX * 128];  // bf16x2 packed agg
__device__ float d_cnt[(size_t)NMAX * 4];        // per (node,etype) in-degree (float)
__device__ float d_WT[(size_t)D * 1024];         // Wstack transposed: [256 out][1024 k]
__device__ float d_pooled[D];
// CSR build
__device__ int d_icnt[(size_t)NMAX * 4];
__device__ int d_cur[(size_t)NMAX * 4];
__device__ int d_off[(size_t)NMAX * 4 + 1];
__device__ int d_bsum[256];
__device__ int d_ss[EMAX];                       // src ids sorted by (dst,type)

// ---------------- bf16 helpers ----------------
__device__ __forceinline__ unsigned pk(float lo, float hi) {
    __nv_bfloat162 t = __floats2bfloat162_rn(lo, hi);
    return *reinterpret_cast<unsigned*>(&t);
}

__device__ __forceinline__ float2 upk(unsigned u) {
    __nv_bfloat162 t = *reinterpret_cast<__nv_bfloat162*>(&u);
    return __bfloat1622float2(t);
}

__device__ __forceinline__ void mma_bf16(float* d, const unsigned* a, const unsigned* b) {
    asm volatile(
        "mma.sync.aligned.m16n8k16.row.col.f32.bf16.bf16.f32 "
        "{%0,%1,%2,%3}, {%4,%5,%6,%7}, {%8,%9}, {%0,%1,%2,%3};\n"
        : "+f"(d[0]), "+f"(d[1]), "+f"(d[2]), "+f"(d[3])
        : "r"(a[0]), "r"(a[1]), "r"(a[2]), "r"(a[3]), "r"(b[0]), "r"(b[1]));
}

__device__ __forceinline__ float sigm(float x) { return 1.f / (1.f + expf(-x)); }

// ---------------- setup helpers ----------------
__global__ void k_zero(float4* __restrict__ p, int n4) {
    int i = blockIdx.x * blockDim.x + threadIdx.x;
    if (i < n4) p[i] = make_float4(0.f, 0.f, 0.f, 0.f);
}

__global__ void k_count_int(const int* __restrict__ dst, const int* __restrict__ typ,
                            int* __restrict__ icnt, int e) {
    int i = blockIdx.x * blockDim.x + threadIdx.x;
    if (i < e) atomicAdd(&icnt[(size_t)dst[i] * 4 + typ[i]], 1);
}

__global__ void k_cnt2float(const int* __restrict__ icnt, float* __restrict__ cnt, int np) {
    int i = blockIdx.x * blockDim.x + threadIdx.x;
    if (i < np) cnt[i] = (float)icnt[i];
}

// exclusive scan, 1024 elems per block
__global__ void k_scan1(const int* __restrict__ in, int* __restrict__ out,
                        int* __restrict__ bsum, int np) {
    __shared__ int sh[256];
    int t = threadIdx.x;
    int base = blockIdx.x * 1024 + t * 4;
    int v0 = (base + 0 < np) ? in[base + 0] : 0;
    int v1 = (base + 1 < np) ? in[base + 1] : 0;
    int v2 = (base + 2 < np) ? in[base + 2] : 0;
    int v3 = (base + 3 < np) ? in[base + 3] : 0;
    int s = v0 + v1 + v2 + v3;
    sh[t] = s;
    __syncthreads();
    for (int ofs = 1; ofs < 256; ofs <<= 1) {
        int x = (t >= ofs) ? sh[t - ofs] : 0;
        __syncthreads();
        sh[t] += x;
        __syncthreads();
    }
    int ex = sh[t] - s;
    if (base + 0 < np) out[base + 0] = ex;
    if (base + 1 < np) out[base + 1] = ex + v0;
    if (base + 2 < np) out[base + 2] = ex + v0 + v1;
    if (base + 3 < np) out[base + 3] = ex + v0 + v1 + v2;
    if (t == 255) bsum[blockIdx.x] = sh[255];
}

__global__ void k_scan2(int* __restrict__ bsum, int nb) {
    __shared__ int sh[256];
    int t = threadIdx.x;
    int v = (t < nb) ? bsum[t] : 0;
    sh[t] = v;
    __syncthreads();
    for (int ofs = 1; ofs < 256; ofs <<= 1) {
        int x = (t >= ofs) ? sh[t - ofs] : 0;
        __syncthreads();
        sh[t] += x;
        __syncthreads();
    }
    if (t < nb) bsum[t] = sh[t] - v;   // exclusive
}

__global__ void k_scan3(int* __restrict__ off, const int* __restrict__ bsum,
                        int np, int total) {
    int add = bsum[blockIdx.x];
    int base = blockIdx.x * 1024 + threadIdx.x * 4;
#pragma unroll
    for (int j = 0; j < 4; j++)
        if (base + j < np) off[base + j] += add;
    if (blockIdx.x == 0 && threadIdx.x == 0) off[np] = total;
}

__global__ void k_place(const int* __restrict__ src, const int* __restrict__ dst,
                        const int* __restrict__ typ, const int* __restrict__ off,
                        int* __restrict__ cur, int* __restrict__ ss, int e) {
    int i = blockIdx.x * blockDim.x + threadIdx.x;
    if (i >= e) return;
    int p = dst[i] * 4 + typ[i];
    int pos = off[p] + atomicAdd(&cur[p], 1);
    ss[pos] = src[i];
}

// h0 = [features | zeros], fp32 + packed bf16
__global__ void k_init_h(const float* __restrict__ f, float* __restrict__ h,
                         unsigned* __restrict__ hbf, int n) {
    int i = blockIdx.x * blockDim.x + threadIdx.x;   // over n*128 pairs
    int m = i >> 7, cp = i & 127;
    if (m >= n) return;
    float v0 = (cp < 64) ? f[(size_t)m * DIN + 2 * cp] : 0.f;
    float v1 = (cp < 64) ? f[(size_t)m * DIN + 2 * cp + 1] : 0.f;
    h[(size_t)m * 256 + 2 * cp] = v0;
    h[(size_t)m * 256 + 2 * cp + 1] = v1;
    hbf[(size_t)m * 128 + cp] = pk(v0, v1);
}

__global__ void k_transpose(const float* __restrict__ W, float* __restrict__ WT) {
    int i = blockIdx.x * blockDim.x + threadIdx.x;
    if (i >= 256 * 1024) return;
    int e = i >> 10, k = i & 1023;
    WT[i] = W[(size_t)k * 256 + e];
}

// ---------------- CSR gather (bf16 h): Sw[p][:] = bf16( sum h[src][:] ) ----
__global__ void k_gather(const unsigned* __restrict__ hbf, const int* __restrict__ ss,
                         const int* __restrict__ off, unsigned* __restrict__ Sw, int np) {
    int p = blockIdx.x * 8 + (threadIdx.x >> 5);
    if (p >= np) return;
    int lane = threadIdx.x & 31;
    int beg = __ldg(off + p), end = __ldg(off + p + 1);
    float a0 = 0.f, a1 = 0.f, a2 = 0.f, a3 = 0.f, a4 = 0.f, a5 = 0.f, a6 = 0.f, a7 = 0.f;
    for (int e = beg; e < end; e++) {
        uint4 w = __ldg((const uint4*)(hbf + (size_t)__ldg(ss + e) * 128 + lane * 4));
        float2 f0 = upk(w.x), f1 = upk(w.y), f2 = upk(w.z), f3 = upk(w.w);
        a0 += f0.x; a1 += f0.y; a2 += f1.x; a3 += f1.y;
        a4 += f2.x; a5 += f2.y; a6 += f3.x; a7 += f3.y;
    }
    uint4 o;
    o.x = pk(a0, a1); o.y = pk(a2, a3); o.z = pk(a4, a5); o.w = pk(a6, a7);
    *reinterpret_cast<uint4*>(Sw + (size_t)p * 128 + lane * 4) = o;
}

// ---------------- agg GEMM: aggw = bf16pack( Sw[M,1024] @ WT^T + cnt-weighted bias ) ----
#define KAGG 1024
__global__ __launch_bounds__(256) void gemm_agg(
    const unsigned* __restrict__ Aw, const float* __restrict__ B,
    unsigned* __restrict__ Cw, int M,
    const float* __restrict__ cnt, const float* __restrict__ bias)
{
    __shared__ unsigned As[2][8][128 + 8];
    __shared__ unsigned Bs[2][8][128 + 8];
    const int tid = threadIdx.x;
    const int bm = blockIdx.y * 128;
    const int bn = blockIdx.x * 128;
    const int lr = tid >> 1;
    const int lh = tid & 1;
    const bool aval = (bm + lr) < M;
    const uint4 zu = make_uint4(0u, 0u, 0u, 0u);

    const unsigned* Awp = Aw + (size_t)(bm + lr) * 512 + lh * 4;
    const float* Bp = B + (size_t)(bn + lr) * KAGG + lh * 8;

    uint4 aw;
    float4 b0, b1;
    aw = aval ? __ldg((const uint4*)Awp) : zu;
    b0 = __ldg((const float4*)Bp);
    b1 = __ldg((const float4*)(Bp + 4));

#define ST_AB(BUF)                                                                \
    do {                                                                          \
        As[BUF][lh * 4 + 0][lr] = aw.x; As[BUF][lh * 4 + 1][lr] = aw.y;           \
        As[BUF][lh * 4 + 2][lr] = aw.z; As[BUF][lh * 4 + 3][lr] = aw.w;           \
        Bs[BUF][lh * 4 + 0][lr] = pk(b0.x, b0.y);                                 \
        Bs[BUF][lh * 4 + 1][lr] = pk(b0.z, b0.w);                                 \
        Bs[BUF][lh * 4 + 2][lr] = pk(b1.x, b1.y);                                 \
        Bs[BUF][lh * 4 + 3][lr] = pk(b1.z, b1.w);                                 \
    } while (0)

    ST_AB(0);
    __syncthreads();

    const int wid = tid >> 5, lane = tid & 31;
    const int wm = (wid & 1) * 64;
    const int wn = (wid >> 1) * 32;
    const int g = lane >> 2, tg = lane & 3;

    float acc[4][4][4];
#pragma unroll
    for (int i = 0; i < 4; i++)
#pragma unroll
        for (int j = 0; j < 4; j++)
#pragma unroll
            for (int q = 0; q < 4; q++) acc[i][j][q] = 0.f;

    int buf = 0;
    for (int k0 = 16; k0 <= KAGG; k0 += 16) {
        const bool more = (k0 < KAGG);
        if (more) {
            aw = aval ? __ldg((const uint4*)(Awp + (k0 >> 1))) : zu;
            b0 = __ldg((const float4*)(Bp + k0));
            b1 = __ldg((const float4*)(Bp + k0 + 4));
        }
        {
            unsigned af[4][4], bfr[4][2];
#pragma unroll
            for (int mi = 0; mi < 4; mi++) {
                int m0 = wm + mi * 16 + g;
                af[mi][0] = As[buf][tg][m0];
                af[mi][1] = As[buf][tg][m0 + 8];
                af[mi][2] = As[buf][tg + 4][m0];
                af[mi][3] = As[buf][tg + 4][m0 + 8];
            }
#pragma unroll
            for (int nj = 0; nj < 4; nj++) {
                int n0 = wn + nj * 8 + g;
                bfr[nj][0] = Bs[buf][tg][n0];
                bfr[nj][1] = Bs[buf][tg + 4][n0];
            }
#pragma unroll
            for (int mi = 0; mi < 4; mi++)
#pragma unroll
                for (int nj = 0; nj < 4; nj++)
                    mma_bf16(acc[mi][nj], af[mi], bfr[nj]);
        }
        if (more) {
            buf ^= 1;
            ST_AB(buf);
            __syncthreads();
        }
    }
#undef ST_AB

    // epilogue: +sum_t cnt[m,t]*bias[t,n], pack to bf16x2
#pragma unroll
    for (int mi = 0; mi < 4; mi++) {
#pragma unroll
        for (int rr = 0; rr < 2; rr++) {
            int m = bm + wm + mi * 16 + g + rr * 8;
            if (m >= M) continue;
            float4 c4 = *reinterpret_cast<const float4*>(cnt + (size_t)m * 4);
            unsigned* Cr = Cw + (size_t)m * 128;
#pragma unroll
            for (int nj = 0; nj < 4; nj++) {
                int c = bn + wn + nj * 8 + 2 * tg;
                float add0 = c4.x * __ldg(bias + 0 * 256 + c) + c4.y * __ldg(bias + 1 * 256 + c)
                           + c4.z * __ldg(bias + 2 * 256 + c) + c4.w * __ldg(bias + 3 * 256 + c);
                float add1 = c4.x * __ldg(bias + 0 * 256 + c + 1) + c4.y * __ldg(bias + 1 * 256 + c + 1)
                           + c4.z * __ldg(bias + 2 * 256 + c + 1) + c4.w * __ldg(bias + 3 * 256 + c + 1);
                Cr[c >> 1] = pk(acc[mi][nj][rr * 2 + 0] + add0,
                                acc[mi][nj][rr * 2 + 1] + add1);
            }
        }
    }
}

// ---------------- fused gates GEMM + GRU ----------------
// 4 accumulator panels over a 128x64 tile of the 256 gate dims:
//   accR = agg@Wih_r^T + h@Whh_r^T   (fused; r only needs the sum)
//   accZ = agg@Wih_z^T + h@Whh_z^T
//   accI = agg@Wih_n^T               (gi_n, needed separately)
//   accH = h@Whh_n^T                 (gh_n)
// Epilogue applies the full GRU; gi is never materialized.
__global__ __launch_bounds__(256) void k_gates(
    const unsigned* __restrict__ aggw, const unsigned* __restrict__ hbfw,
    const float* __restrict__ hin,
    const float* __restrict__ Wih, const float* __restrict__ Whh,
    const float* __restrict__ bih, const float* __restrict__ bhh,
    float* __restrict__ hout, unsigned* __restrict__ hbfout, int M)
{
    __shared__ unsigned Aa[2][8][128 + 8];
    __shared__ unsigned Ah[2][8][128 + 8];
    __shared__ unsigned Bs[2][6][8][64 + 8];
    const int tid = threadIdx.x;
    const int bm = blockIdx.y * 128;
    const int bn = blockIdx.x * 64;
    const int ar = tid & 127;          // A row
    const int ahw = tid >> 7;          // A k-half (4 words)
    const bool aval = (bm + ar) < M;
    const uint4 zu = make_uint4(0u, 0u, 0u, 0u);

    const unsigned* Aap = aggw + (size_t)(bm + ar) * 128 + ahw * 4;
    const unsigned* Ahp = hbfw + (size_t)(bm + ar) * 128 + ahw * 4;

    // B rows: rr = tid covers panels 0..3; rr = tid+256 (tid<128) covers panels 4..5
    // panel p: 0..2 = Wih gates r,z,n; 3..5 = Whh gates r,z,n
    const int p1 = tid >> 6;                   // 0..3
    const int n1 = tid & 63;
    const float* B1 = (p1 < 3) ? (Wih + (size_t)(p1 * 256 + bn + n1) * 256)
                               : (Whh + (size_t)(0 * 256 + bn + n1) * 256);
    const int p2 = 4 + (tid >> 6);             // 4..5 valid for tid<128
    const float* B2 = (tid < 128) ? (Whh + (size_t)((p2 - 3) * 256 + bn + n1) * 256) : Whh;
    const bool b2act = (tid < 128);

    uint4 a1, a2;
    float4 q1[4], q2[4];
    a1 = aval ? __ldg((const uint4*)Aap) : zu;
    a2 = aval ? __ldg((const uint4*)Ahp) : zu;
#pragma unroll
    for (int j = 0; j < 4; j++) q1[j] = __ldg((const float4*)B1 + j);
    if (b2act) {
#pragma unroll
        for (int j = 0; j < 4; j++) q2[j] = __ldg((const float4*)B2 + j);
    }

#define ST_GT(BUF)                                                                \
    do {                                                                          \
        Aa[BUF][ahw * 4 + 0][ar] = a1.x; Aa[BUF][ahw * 4 + 1][ar] = a1.y;         \
        Aa[BUF][ahw * 4 + 2][ar] = a1.z; Aa[BUF][ahw * 4 + 3][ar] = a1.w;         \
        Ah[BUF][ahw * 4 + 0][ar] = a2.x; Ah[BUF][ahw * 4 + 1][ar] = a2.y;         \
        Ah[BUF][ahw * 4 + 2][ar] = a2.z; Ah[BUF][ahw * 4 + 3][ar] = a2.w;         \
        _Pragma("unroll")                                                         \
        for (int j = 0; j < 4; j++) {                                             \
            Bs[BUF][p1][2 * j + 0][n1] = pk(q1[j].x, q1[j].y);                    \
            Bs[BUF][p1][2 * j + 1][n1] = pk(q1[j].z, q1[j].w);                    \
        }                                                                         \
        if (b2act) {                                                              \
            _Pragma("unroll")                                                     \
            for (int j = 0; j < 4; j++) {                                         \
                Bs[BUF][p2][2 * j + 0][n1] = pk(q2[j].x, q2[j].y);                \
                Bs[BUF][p2][2 * j + 1][n1] = pk(q2[j].z, q2[j].w);                \
            }                                                                     \
        }                                                                         \
    } while (0)

    ST_GT(0);
    __syncthreads();

    const int wid = tid >> 5, lane = tid & 31;
    const int wm = (wid & 1) * 64;     // 2 warps along M
    const int wn = (wid >> 1) * 16;    // 4 warps along N (16 cols each)
    const int g = lane >> 2, tg = lane & 3;

    float accR[4][2][4], accZ[4][2][4], accI[4][2][4], accH[4][2][4];
#pragma unroll
    for (int i = 0; i < 4; i++)
#pragma unroll
        for (int j = 0; j < 2; j++)
#pragma unroll
            for (int q = 0; q < 4; q++) {
                accR[i][j][q] = 0.f; accZ[i][j][q] = 0.f;
                accI[i][j][q] = 0.f; accH[i][j][q] = 0.f;
            }

    int buf = 0;
    for (int k0 = 16; k0 <= 256; k0 += 16) {
        const bool more = (k0 < 256);
        if (more) {
            a1 = aval ? __ldg((const uint4*)(Aap + (k0 >> 1))) : zu;
            a2 = aval ? __ldg((const uint4*)(Ahp + (k0 >> 1))) : zu;
#pragma unroll
            for (int j = 0; j < 4; j++) q1[j] = __ldg((const float4*)(B1 + k0) + j);
            if (b2act) {
#pragma unroll
                for (int j = 0; j < 4; j++) q2[j] = __ldg((const float4*)(B2 + k0) + j);
            }
        }
        {
            unsigned afa[4][4], afh[4][4], bfr[6][2][2];
#pragma unroll
            for (int mi = 0; mi < 4; mi++) {
                int m0 = wm + mi * 16 + g;
                afa[mi][0] = Aa[buf][tg][m0];     afa[mi][1] = Aa[buf][tg][m0 + 8];
                afa[mi][2] = Aa[buf][tg + 4][m0]; afa[mi][3] = Aa[buf][tg + 4][m0 + 8];
                afh[mi][0] = Ah[buf][tg][m0];     afh[mi][1] = Ah[buf][tg][m0 + 8];
                afh[mi][2] = Ah[buf][tg + 4][m0]; afh[mi][3] = Ah[buf][tg + 4][m0 + 8];
            }
#pragma unroll
            for (int p = 0; p < 6; p++)
#pragma unroll
                for (int nj = 0; nj < 2; nj++) {
                    int n0 = wn + nj * 8 + g;
                    bfr[p][nj][0] = Bs[buf][p][tg][n0];
                    bfr[p][nj][1] = Bs[buf][p][tg + 4][n0];
                }
#pragma unroll
            for (int mi = 0; mi < 4; mi++)
#pragma unroll
                for (int nj = 0; nj < 2; nj++) {
                    mma_bf16(accR[mi][nj], afa[mi], bfr[0][nj]);
                    mma_bf16(accR[mi][nj], afh[mi], bfr[3][nj]);
                    mma_bf16(accZ[mi][nj], afa[mi], bfr[1][nj]);
                    mma_bf16(accZ[mi][nj], afh[mi], bfr[4][nj]);
                    mma_bf16(accI[mi][nj], afa[mi], bfr[2][nj]);
                    mma_bf16(accH[mi][nj], afh[mi], bfr[5][nj]);
                }
        }
        if (more) {
            buf ^= 1;
            ST_GT(buf);
            __syncthreads();
        }
    }
#undef ST_GT

    // GRU epilogue; biases hoisted per column
    float brz[2][2][2], bzz[2][2][2], bin[2][2], bhn[2][2];
#pragma unroll
    for (int nj = 0; nj < 2; nj++)
#pragma unroll
        for (int j = 0; j < 2; j++) {
            int cc = bn + wn + nj * 8 + 2 * tg + j;
            brz[nj][j][0] = __ldg(bih + cc) + __ldg(bhh + cc);
            bzz[nj][j][0] = __ldg(bih + 256 + cc) + __ldg(bhh + 256 + cc);
            bin[nj][j] = __ldg(bih + 512 + cc);
            bhn[nj][j] = __ldg(bhh + 512 + cc);
            brz[nj][j][1] = 0.f; bzz[nj][j][1] = 0.f;  // unused halves
        }

#pragma unroll
    for (int mi = 0; mi < 4; mi++) {
#pragma unroll
        for (int rr = 0; rr < 2; rr++) {
            int m = bm + wm + mi * 16 + g + rr * 8;
            if (m >= M) continue;
#pragma unroll
            for (int nj = 0; nj < 2; nj++) {
                int c = bn + wn + nj * 8 + 2 * tg;
                float2 hv = *reinterpret_cast<const float2*>(hin + (size_t)m * 256 + c);
                float o01[2];
#pragma unroll
                for (int j = 0; j < 2; j++) {
                    int q = rr * 2 + j;
                    float r = sigm(accR[mi][nj][q] + brz[nj][j][0]);
                    float z = sigm(accZ[mi][nj][q] + bzz[nj][j][0]);
                    float gin = accI[mi][nj][q] + bin[nj][j];
                    float ghn = accH[mi][nj][q] + bhn[nj][j];
                    float nn = tanhf(gin + r * ghn);
                    float hj = j ? hv.y : hv.x;
                    o01[j] = (1.f - z) * nn + z * hj;
                }
                *reinterpret_cast<float2*>(hout + (size_t)m * 256 + c) =
                    make_float2(o01[0], o01[1]);
                hbfout[(size_t)m * 128 + (c >> 1)] = pk(o01[0], o01[1]);
            }
        }
    }
}

// ---------------- pooling + classifier ----------------
__global__ void k_pool(const float* __restrict__ h, float* __restrict__ pooled, int M) {
    int c = threadIdx.x;
    int r0 = blockIdx.x * 256;
    int rend = min(r0 + 256, M);
    float s = 0.f;
    for (int r = r0; r < rend; r++) s += h[(size_t)r * 256 + c];
    atomicAdd(&pooled[c], s);
}

__global__ void k_final(const float* __restrict__ pooled, const float* __restrict__ Wc,
                        const float* __restrict__ bc, float* __restrict__ out) {
    __shared__ float red[256];
    int t = threadIdx.x;
    red[t] = pooled[t] * Wc[t];
    __syncthreads();
    for (int s = 128; s > 0; s >>= 1) {
        if (t < s) red[t] += red[t + s];
        __syncthreads();
    }
    if (t == 0) out[0] = 1.f / (1.f + expf(-(red[0] + bc[0])));
}

// ---------------- launch ----------------
extern "C" void kernel_launch(void* const* d_in, const int* in_sizes, int n_in,
                              void* d_out, int out_size) {
    const float* features = (const float*)d_in[0];
    const int* esrc = (const int*)d_in[1];
    const int* edst = (const int*)d_in[2];
    const int* etyp = (const int*)d_in[3];
    const float* W   = (const float*)d_in[4];
    const float* b   = (const float*)d_in[5];
    const float* Wih = (const float*)d_in[6];
    const float* Whh = (const float*)d_in[7];
    const float* bih = (const float*)d_in[8];
    const float* bhh = (const float*)d_in[9];
    const float* Wc  = (const float*)d_in[10];
    const float* bc  = (const float*)d_in[11];
    float* out = (float*)d_out;

    const int M = in_sizes[0] / DIN;   // 50000
    const int E = in_sizes[1];         // 800000
    const int np = M * 4;              // 200000 (dst,type) buckets

    unsigned *Sw, *hbfA, *hbfB, *aggw;
    float *hA, *hB, *cnt, *WT, *pooled;
    int *icnt, *cur, *off, *bsum, *ss;
    cudaGetSymbolAddress((void**)&Sw, d_Sw);
    cudaGetSymbolAddress((void**)&hA, d_hA);
    cudaGetSymbolAddress((void**)&hB, d_hB);
    cudaGetSymbolAddress((void**)&hbfA, d_hbfA);
    cudaGetSymbolAddress((void**)&hbfB, d_hbfB);
    cudaGetSymbolAddress((void**)&aggw, d_aggw);
    cudaGetSymbolAddress((void**)&cnt, d_cnt);
    cudaGetSymbolAddress((void**)&WT, d_WT);
    cudaGetSymbolAddress((void**)&pooled, d_pooled);
    cudaGetSymbolAddress((void**)&icnt, d_icnt);
    cudaGetSymbolAddress((void**)&cur, d_cur);
    cudaGetSymbolAddress((void**)&off, d_off);
    cudaGetSymbolAddress((void**)&bsum, d_bsum);
    cudaGetSymbolAddress((void**)&ss, d_ss);

    // ---- one-time (per launch) setup: CSR build + h0 + WT ----
    const int nb = (np + 1023) / 1024;
    k_zero<<<(np / 4 + 255) / 256, 256>>>((float4*)icnt, np / 4);
    k_zero<<<(np / 4 + 255) / 256, 256>>>((float4*)cur, np / 4);
    k_count_int<<<(E + 255) / 256, 256>>>(edst, etyp, icnt, E);
    k_cnt2float<<<(np + 255) / 256, 256>>>(icnt, cnt, np);
    k_scan1<<<nb, 256>>>(icnt, off, bsum, np);
    k_scan2<<<1, 256>>>(bsum, nb);
    k_scan3<<<nb, 256>>>(off, bsum, np, E);
    k_place<<<(E + 255) / 256, 256>>>(esrc, edst, etyp, off, cur, ss, E);
    k_init_h<<<((size_t)M * 128 + 255) / 256, 256>>>(features, hA, hbfA, M);
    k_transpose<<<(256 * 1024 + 255) / 256, 256>>>(W, WT);

    float* hin = hA;  float* hout = hB;
    unsigned* hbfin = hbfA;  unsigned* hbfout = hbfB;
    const int mb = (M + 127) / 128;
    dim3 gAgg(2, mb), gGates(4, mb);
    const int gGather = (np + 7) / 8;

    for (int step = 0; step < 8; step++) {
        k_gather<<<gGather, 256>>>(hbfin, ss, off, Sw, np);
        gemm_agg<<<gAgg, 256>>>(Sw, WT, aggw, M, cnt, b);
        k_gates<<<gGates, 256>>>(aggw, hbfin, hin, Wih, Whh, bih, bhh, hout, hbfout, M);
        float* t = hin; hin = hout; hout = t;
        unsigned* tw = hbfin; hbfin = hbfout; hbfout = tw;
    }

    k_zero<<<1, 64>>>((float4*)pooled, 64);
    k_pool<<<(M + 255) / 256, 256>>>(hin, pooled, M);
    k_final<<<1, 256>>>(pooled, Wc, bc, out);
}

// round 13
// speedup vs baseline: 3.2911x; 1.1047x over previous
#include <cuda_runtime.h>
#include <cuda_bf16.h>
#include <math.h>

#define NMAX 50000
#define EMAX 800000
#define D 256
#define DIN 128

// ---------------- scratch (static device globals; no allocation) ----------------
__device__ unsigned d_Sw[(size_t)NMAX * 512];    // [N*4 buckets][128 words] bf16x2 neighbor sums
__device__ float d_hA[(size_t)NMAX * D];
__device__ float d_hB[(size_t)NMAX * D];
__device__ unsigned d_hbfA[(size_t)NMAX * 128];  // bf16x2 packed h (ping)
__device__ unsigned d_hbfB[(size_t)NMAX * 128];  // bf16x2 packed h (pong)
__device__ unsigned d_aggw[(size_t)NMAX * 128];  // bf16x2 packed agg
__device__ float d_cnt[(size_t)NMAX * 4];
__device__ float d_WT[(size_t)D * 1024];         // Wstack transposed: [256 out][1024 k]
__device__ float d_pooled[D];
// CSR build
__device__ int d_icnt[(size_t)NMAX * 4];
__device__ int d_cur[(size_t)NMAX * 4];
__device__ int d_off[(size_t)NMAX * 4 + 1];
__device__ int d_bsum[256];
__device__ int d_ss[EMAX];

// ---------------- bf16 / mma helpers ----------------
__device__ __forceinline__ unsigned pk(float lo, float hi) {
    __nv_bfloat162 t = __floats2bfloat162_rn(lo, hi);
    return *reinterpret_cast<unsigned*>(&t);
}

__device__ __forceinline__ float2 upk(unsigned u) {
    __nv_bfloat162 t = *reinterpret_cast<__nv_bfloat162*>(&u);
    return __bfloat1622float2(t);
}

__device__ __forceinline__ void mma_bf16(float* d, const unsigned* a, const unsigned* b) {
    asm volatile(
        "mma.sync.aligned.m16n8k16.row.col.f32.bf16.bf16.f32 "
        "{%0,%1,%2,%3}, {%4,%5,%6,%7}, {%8,%9}, {%0,%1,%2,%3};\n"
        : "+f"(d[0]), "+f"(d[1]), "+f"(d[2]), "+f"(d[3])
        : "r"(a[0]), "r"(a[1]), "r"(a[2]), "r"(a[3]), "r"(b[0]), "r"(b[1]));
}

__device__ __forceinline__ void ldsm_x4(unsigned& r0, unsigned& r1, unsigned& r2,
                                        unsigned& r3, unsigned addr) {
    asm volatile("ldmatrix.sync.aligned.m8n8.x4.shared.b16 {%0,%1,%2,%3}, [%4];"
                 : "=r"(r0), "=r"(r1), "=r"(r2), "=r"(r3) : "r"(addr));
}

__device__ __forceinline__ float sigm(float x) { return 1.f / (1.f + expf(-x)); }

// swizzled word index for (row, chunk) in a row-major 32B-row tile
__device__ __forceinline__ unsigned sw_idx(int row, int chunk) {
    return (unsigned)(row * 8 + ((chunk ^ ((row >> 2) & 1)) * 4));
}
// swizzled byte offset for ldmatrix lane (row, chunk)
__device__ __forceinline__ unsigned sw_off(int row, int chunk) {
    return (unsigned)(row * 32 + ((chunk ^ ((row >> 2) & 1)) * 16));
}

// ---------------- setup helpers ----------------
__global__ void k_zero(float4* __restrict__ p, int n4) {
    int i = blockIdx.x * blockDim.x + threadIdx.x;
    if (i < n4) p[i] = make_float4(0.f, 0.f, 0.f, 0.f);
}

__global__ void k_count_int(const int* __restrict__ dst, const int* __restrict__ typ,
                            int* __restrict__ icnt, int e) {
    int i = blockIdx.x * blockDim.x + threadIdx.x;
    if (i < e) atomicAdd(&icnt[(size_t)dst[i] * 4 + typ[i]], 1);
}

__global__ void k_cnt2float(const int* __restrict__ icnt, float* __restrict__ cnt, int np) {
    int i = blockIdx.x * blockDim.x + threadIdx.x;
    if (i < np) cnt[i] = (float)icnt[i];
}

__global__ void k_scan1(const int* __restrict__ in, int* __restrict__ out,
                        int* __restrict__ bsum, int np) {
    __shared__ int sh[256];
    int t = threadIdx.x;
    int base = blockIdx.x * 1024 + t * 4;
    int v0 = (base + 0 < np) ? in[base + 0] : 0;
    int v1 = (base + 1 < np) ? in[base + 1] : 0;
    int v2 = (base + 2 < np) ? in[base + 2] : 0;
    int v3 = (base + 3 < np) ? in[base + 3] : 0;
    int s = v0 + v1 + v2 + v3;
    sh[t] = s;
    __syncthreads();
    for (int ofs = 1; ofs < 256; ofs <<= 1) {
        int x = (t >= ofs) ? sh[t - ofs] : 0;
        __syncthreads();
        sh[t] += x;
        __syncthreads();
    }
    int ex = sh[t] - s;
    if (base + 0 < np) out[base + 0] = ex;
    if (base + 1 < np) out[base + 1] = ex + v0;
    if (base + 2 < np) out[base + 2] = ex + v0 + v1;
    if (base + 3 < np) out[base + 3] = ex + v0 + v1 + v2;
    if (t == 255) bsum[blockIdx.x] = sh[255];
}

__global__ void k_scan2(int* __restrict__ bsum, int nb) {
    __shared__ int sh[256];
    int t = threadIdx.x;
    int v = (t < nb) ? bsum[t] : 0;
    sh[t] = v;
    __syncthreads();
    for (int ofs = 1; ofs < 256; ofs <<= 1) {
        int x = (t >= ofs) ? sh[t - ofs] : 0;
        __syncthreads();
        sh[t] += x;
        __syncthreads();
    }
    if (t < nb) bsum[t] = sh[t] - v;
}

__global__ void k_scan3(int* __restrict__ off, const int* __restrict__ bsum,
                        int np, int total) {
    int add = bsum[blockIdx.x];
    int base = blockIdx.x * 1024 + threadIdx.x * 4;
#pragma unroll
    for (int j = 0; j < 4; j++)
        if (base + j < np) off[base + j] += add;
    if (blockIdx.x == 0 && threadIdx.x == 0) off[np] = total;
}

__global__ void k_place(const int* __restrict__ src, const int* __restrict__ dst,
                        const int* __restrict__ typ, const int* __restrict__ off,
                        int* __restrict__ cur, int* __restrict__ ss, int e) {
    int i = blockIdx.x * blockDim.x + threadIdx.x;
    if (i >= e) return;
    int p = dst[i] * 4 + typ[i];
    int pos = off[p] + atomicAdd(&cur[p], 1);
    ss[pos] = src[i];
}

__global__ void k_init_h(const float* __restrict__ f, float* __restrict__ h,
                         unsigned* __restrict__ hbf, int n) {
    int i = blockIdx.x * blockDim.x + threadIdx.x;
    int m = i >> 7, cp = i & 127;
    if (m >= n) return;
    float v0 = (cp < 64) ? f[(size_t)m * DIN + 2 * cp] : 0.f;
    float v1 = (cp < 64) ? f[(size_t)m * DIN + 2 * cp + 1] : 0.f;
    h[(size_t)m * 256 + 2 * cp] = v0;
    h[(size_t)m * 256 + 2 * cp + 1] = v1;
    hbf[(size_t)m * 128 + cp] = pk(v0, v1);
}

__global__ void k_transpose(const float* __restrict__ W, float* __restrict__ WT) {
    int i = blockIdx.x * blockDim.x + threadIdx.x;
    if (i >= 256 * 1024) return;
    int e = i >> 10, k = i & 1023;
    WT[i] = W[(size_t)k * 256 + e];
}

// ---------------- CSR gather (bf16 h) ----------------
__global__ void k_gather(const unsigned* __restrict__ hbf, const int* __restrict__ ss,
                         const int* __restrict__ off, unsigned* __restrict__ Sw, int np) {
    int p = blockIdx.x * 8 + (threadIdx.x >> 5);
    if (p >= np) return;
    int lane = threadIdx.x & 31;
    int beg = __ldg(off + p), end = __ldg(off + p + 1);
    float a0 = 0.f, a1 = 0.f, a2 = 0.f, a3 = 0.f, a4 = 0.f, a5 = 0.f, a6 = 0.f, a7 = 0.f;
    for (int e = beg; e < end; e++) {
        uint4 w = __ldg((const uint4*)(hbf + (size_t)__ldg(ss + e) * 128 + lane * 4));
        float2 f0 = upk(w.x), f1 = upk(w.y), f2 = upk(w.z), f3 = upk(w.w);
        a0 += f0.x; a1 += f0.y; a2 += f1.x; a3 += f1.y;
        a4 += f2.x; a5 += f2.y; a6 += f3.x; a7 += f3.y;
    }
    uint4 o;
    o.x = pk(a0, a1); o.y = pk(a2, a3); o.z = pk(a4, a5); o.w = pk(a6, a7);
    *reinterpret_cast<uint4*>(Sw + (size_t)p * 128 + lane * 4) = o;
}

// ---------------- agg GEMM (ldmatrix): aggw = bf16( Sw[M,1024] @ WT^T + cnt·bias ) ----
#define KAGG 1024
__global__ __launch_bounds__(256) void gemm_agg(
    const unsigned* __restrict__ Aw, const float* __restrict__ B,
    unsigned* __restrict__ Cw, int M,
    const float* __restrict__ cnt, const float* __restrict__ bias)
{
    __shared__ unsigned As[2][1024];   // 128 rows x 8 words (32B rows, swizzled)
    __shared__ unsigned Bs[2][1024];
    const int tid = threadIdx.x;
    const int bm = blockIdx.y * 128;
    const int bn = blockIdx.x * 128;
    const int lr = tid >> 1;
    const int lh = tid & 1;
    const bool aval = (bm + lr) < M;
    const uint4 zu = make_uint4(0u, 0u, 0u, 0u);

    const unsigned* Awp = Aw + (size_t)(bm + lr) * 512 + lh * 4;
    const float* Bp = B + (size_t)(bn + lr) * KAGG + lh * 8;
    const unsigned siA = sw_idx(lr, lh);
    const unsigned siB = siA;

    uint4 aw;
    float4 b0, b1;
    aw = aval ? __ldg((const uint4*)Awp) : zu;
    b0 = __ldg((const float4*)Bp);
    b1 = __ldg((const float4*)(Bp + 4));

#define ST_AB(BUF)                                                                \
    do {                                                                          \
        *(uint4*)&As[BUF][siA] = aw;                                              \
        *(uint4*)&Bs[BUF][siB] = make_uint4(pk(b0.x, b0.y), pk(b0.z, b0.w),       \
                                            pk(b1.x, b1.y), pk(b1.z, b1.w));      \
    } while (0)

    ST_AB(0);
    __syncthreads();

    const int wid = tid >> 5, lane = tid & 31;
    const int wm = (wid & 1) * 64;
    const int wn = (wid >> 1) * 32;
    const int g = lane >> 2, tg = lane & 3;
    (void)g; (void)tg;

    const unsigned sAb = (unsigned)__cvta_generic_to_shared(&As[0][0]);
    const unsigned sBb = (unsigned)__cvta_generic_to_shared(&Bs[0][0]);
    const int lrow = (lane & 7) + ((lane >> 3) & 1) * 8;
    const int lc = (lane >> 4) & 1;
    unsigned aoff[4], boff[2];
#pragma unroll
    for (int mi = 0; mi < 4; mi++) aoff[mi] = sw_off(wm + mi * 16 + lrow, lc);
#pragma unroll
    for (int nt = 0; nt < 2; nt++) boff[nt] = sw_off(wn + nt * 16 + lrow, lc);

    float acc[4][4][4];
#pragma unroll
    for (int i = 0; i < 4; i++)
#pragma unroll
        for (int j = 0; j < 4; j++)
#pragma unroll
            for (int q = 0; q < 4; q++) acc[i][j][q] = 0.f;

    int buf = 0;
    for (int k0 = 16; k0 <= KAGG; k0 += 16) {
        const bool more = (k0 < KAGG);
        if (more) {
            aw = aval ? __ldg((const uint4*)(Awp + (k0 >> 1))) : zu;
            b0 = __ldg((const float4*)(Bp + k0));
            b1 = __ldg((const float4*)(Bp + k0 + 4));
        }
        {
            const unsigned ab = sAb + buf * 4096;
            const unsigned bb = sBb + buf * 4096;
            unsigned af[4][4], bfr[4][2];
#pragma unroll
            for (int mi = 0; mi < 4; mi++)
                ldsm_x4(af[mi][0], af[mi][1], af[mi][2], af[mi][3], ab + aoff[mi]);
#pragma unroll
            for (int nt = 0; nt < 2; nt++) {
                unsigned r0, r1, r2, r3;
                ldsm_x4(r0, r1, r2, r3, bb + boff[nt]);
                bfr[nt * 2 + 0][0] = r0; bfr[nt * 2 + 0][1] = r2;
                bfr[nt * 2 + 1][0] = r1; bfr[nt * 2 + 1][1] = r3;
            }
#pragma unroll
            for (int mi = 0; mi < 4; mi++)
#pragma unroll
                for (int nj = 0; nj < 4; nj++)
                    mma_bf16(acc[mi][nj], af[mi], bfr[nj]);
        }
        if (more) {
            buf ^= 1;
            ST_AB(buf);
            __syncthreads();
        }
    }
#undef ST_AB

    // epilogue: +sum_t cnt[m,t]*bias[t,n], pack to bf16x2
    const int eg = lane >> 2, etg = lane & 3;
#pragma unroll
    for (int mi = 0; mi < 4; mi++) {
#pragma unroll
        for (int rr = 0; rr < 2; rr++) {
            int m = bm + wm + mi * 16 + eg + rr * 8;
            if (m >= M) continue;
            float4 c4 = *reinterpret_cast<const float4*>(cnt + (size_t)m * 4);
            unsigned* Cr = Cw + (size_t)m * 128;
#pragma unroll
            for (int nj = 0; nj < 4; nj++) {
                int c = bn + wn + nj * 8 + 2 * etg;
                float add0 = c4.x * __ldg(bias + 0 * 256 + c) + c4.y * __ldg(bias + 1 * 256 + c)
                           + c4.z * __ldg(bias + 2 * 256 + c) + c4.w * __ldg(bias + 3 * 256 + c);
                float add1 = c4.x * __ldg(bias + 0 * 256 + c + 1) + c4.y * __ldg(bias + 1 * 256 + c + 1)
                           + c4.z * __ldg(bias + 2 * 256 + c + 1) + c4.w * __ldg(bias + 3 * 256 + c + 1);
                Cr[c >> 1] = pk(acc[mi][nj][rr * 2 + 0] + add0,
                                acc[mi][nj][rr * 2 + 1] + add1);
            }
        }
    }
}

// ---------------- fused gates GEMM + GRU (ldmatrix) ----------------
__global__ __launch_bounds__(256) void k_gates(
    const unsigned* __restrict__ aggw, const unsigned* __restrict__ hbfw,
    const float* __restrict__ hin,
    const float* __restrict__ Wih, const float* __restrict__ Whh,
    const float* __restrict__ bih, const float* __restrict__ bhh,
    float* __restrict__ hout, unsigned* __restrict__ hbfout, int M)
{
    __shared__ unsigned Aa[2][1024];    // 128 rows x 8 words
    __shared__ unsigned Ah[2][1024];
    __shared__ unsigned Bsx[2][3072];   // 384 rows (6 panels x 64) x 8 words
    const int tid = threadIdx.x;
    const int bm = blockIdx.y * 128;
    const int bn = blockIdx.x * 64;
    const int ar = tid & 127;
    const int ahw = tid >> 7;
    const bool aval = (bm + ar) < M;
    const uint4 zu = make_uint4(0u, 0u, 0u, 0u);

    const unsigned* Aap = aggw + (size_t)(bm + ar) * 128 + ahw * 4;
    const unsigned* Ahp = hbfw + (size_t)(bm + ar) * 128 + ahw * 4;
    const unsigned siAa = sw_idx(ar, ahw);

    // B rows: panels 0..2 = Wih gates r,z,n; 3..5 = Whh gates r,z,n
    const int p1 = tid >> 6;
    const int n1 = tid & 63;
    const float* B1 = (p1 < 3) ? (Wih + (size_t)(p1 * 256 + bn + n1) * 256)
                               : (Whh + (size_t)(0 * 256 + bn + n1) * 256);
    const int p2 = 4 + (tid >> 6);
    const float* B2 = (tid < 128) ? (Whh + (size_t)((p2 - 3) * 256 + bn + n1) * 256) : Whh;
    const bool b2act = (tid < 128);
    const int R1 = p1 * 64 + n1;
    const int R2 = (tid < 128) ? (p2 * 64 + n1) : 0;
    const unsigned siB1c0 = sw_idx(R1, 0), siB1c1 = sw_idx(R1, 1);
    const unsigned siB2c0 = sw_idx(R2, 0), siB2c1 = sw_idx(R2, 1);

    uint4 a1, a2;
    float4 q1[4], q2[4];
    a1 = aval ? __ldg((const uint4*)Aap) : zu;
    a2 = aval ? __ldg((const uint4*)Ahp) : zu;
#pragma unroll
    for (int j = 0; j < 4; j++) q1[j] = __ldg((const float4*)B1 + j);
    if (b2act) {
#pragma unroll
        for (int j = 0; j < 4; j++) q2[j] = __ldg((const float4*)B2 + j);
    }

#define ST_GT(BUF)                                                                \
    do {                                                                          \
        *(uint4*)&Aa[BUF][siAa] = a1;                                             \
        *(uint4*)&Ah[BUF][siAa] = a2;                                             \
        *(uint4*)&Bsx[BUF][siB1c0] = make_uint4(pk(q1[0].x, q1[0].y), pk(q1[0].z, q1[0].w), \
                                                pk(q1[1].x, q1[1].y), pk(q1[1].z, q1[1].w)); \
        *(uint4*)&Bsx[BUF][siB1c1] = make_uint4(pk(q1[2].x, q1[2].y), pk(q1[2].z, q1[2].w), \
                                                pk(q1[3].x, q1[3].y), pk(q1[3].z, q1[3].w)); \
        if (b2act) {                                                              \
            *(uint4*)&Bsx[BUF][siB2c0] = make_uint4(pk(q2[0].x, q2[0].y), pk(q2[0].z, q2[0].w), \
                                                    pk(q2[1].x, q2[1].y), pk(q2[1].z, q2[1].w)); \
            *(uint4*)&Bsx[BUF][siB2c1] = make_uint4(pk(q2[2].x, q2[2].y), pk(q2[2].z, q2[2].w), \
                                                    pk(q2[3].x, q2[3].y), pk(q2[3].z, q2[3].w)); \
        }                                                                         \
    } while (0)

    ST_GT(0);
    __syncthreads();

    const int wid = tid >> 5, lane = tid & 31;
    const int wm = (wid & 1) * 64;
    const int wn = (wid >> 1) * 16;
    const int g = lane >> 2, tg = lane & 3;
    (void)g; (void)tg;

    const unsigned sAab = (unsigned)__cvta_generic_to_shared(&Aa[0][0]);
    const unsigned sAhb = (unsigned)__cvta_generic_to_shared(&Ah[0][0]);
    const unsigned sBxb = (unsigned)__cvta_generic_to_shared(&Bsx[0][0]);
    const int lrow = (lane & 7) + ((lane >> 3) & 1) * 8;
    const int lc = (lane >> 4) & 1;
    unsigned aoff[4], bpoff[6];
#pragma unroll
    for (int mi = 0; mi < 4; mi++) aoff[mi] = sw_off(wm + mi * 16 + lrow, lc);
#pragma unroll
    for (int p = 0; p < 6; p++) bpoff[p] = sw_off(p * 64 + wn + lrow, lc);

    float accR[4][2][4], accZ[4][2][4], accI[4][2][4], accH[4][2][4];
#pragma unroll
    for (int i = 0; i < 4; i++)
#pragma unroll
        for (int j = 0; j < 2; j++)
#pragma unroll
            for (int q = 0; q < 4; q++) {
                accR[i][j][q] = 0.f; accZ[i][j][q] = 0.f;
                accI[i][j][q] = 0.f; accH[i][j][q] = 0.f;
            }

    int buf = 0;
    for (int k0 = 16; k0 <= 256; k0 += 16) {
        const bool more = (k0 < 256);
        if (more) {
            a1 = aval ? __ldg((const uint4*)(Aap + (k0 >> 1))) : zu;
            a2 = aval ? __ldg((const uint4*)(Ahp + (k0 >> 1))) : zu;
#pragma unroll
            for (int j = 0; j < 4; j++) q1[j] = __ldg((const float4*)(B1 + k0) + j);
            if (b2act) {
#pragma unroll
                for (int j = 0; j < 4; j++) q2[j] = __ldg((const float4*)(B2 + k0) + j);
            }
        }
        {
            const unsigned ab = sAab + buf * 4096;
            const unsigned hb = sAhb + buf * 4096;
            const unsigned bb = sBxb + buf * 12288;
            unsigned afa[4][4], afh[4][4], bfr[6][2][2];
#pragma unroll
            for (int mi = 0; mi < 4; mi++) {
                ldsm_x4(afa[mi][0], afa[mi][1], afa[mi][2], afa[mi][3], ab + aoff[mi]);
                ldsm_x4(afh[mi][0], afh[mi][1], afh[mi][2], afh[mi][3], hb + aoff[mi]);
            }
#pragma unroll
            for (int p = 0; p < 6; p++) {
                unsigned r0, r1, r2, r3;
                ldsm_x4(r0, r1, r2, r3, bb + bpoff[p]);
                bfr[p][0][0] = r0; bfr[p][0][1] = r2;
                bfr[p][1][0] = r1; bfr[p][1][1] = r3;
            }
#pragma unroll
            for (int mi = 0; mi < 4; mi++)
#pragma unroll
                for (int nj = 0; nj < 2; nj++) {
                    mma_bf16(accR[mi][nj], afa[mi], bfr[0][nj]);
                    mma_bf16(accR[mi][nj], afh[mi], bfr[3][nj]);
                    mma_bf16(accZ[mi][nj], afa[mi], bfr[1][nj]);
                    mma_bf16(accZ[mi][nj], afh[mi], bfr[4][nj]);
                    mma_bf16(accI[mi][nj], afa[mi], bfr[2][nj]);
                    mma_bf16(accH[mi][nj], afh[mi], bfr[5][nj]);
                }
        }
        if (more) {
            buf ^= 1;
            ST_GT(buf);
            __syncthreads();
        }
    }
#undef ST_GT

    // GRU epilogue
    const int eg = lane >> 2, etg = lane & 3;
    float brz[2][2], bzz[2][2], bin[2][2], bhn[2][2];
#pragma unroll
    for (int nj = 0; nj < 2; nj++)
#pragma unroll
        for (int j = 0; j < 2; j++) {
            int cc = bn + wn + nj * 8 + 2 * etg + j;
            brz[nj][j] = __ldg(bih + cc) + __ldg(bhh + cc);
            bzz[nj][j] = __ldg(bih + 256 + cc) + __ldg(bhh + 256 + cc);
            bin[nj][j] = __ldg(bih + 512 + cc);
            bhn[nj][j] = __ldg(bhh + 512 + cc);
        }

#pragma unroll
    for (int mi = 0; mi < 4; mi++) {
#pragma unroll
        for (int rr = 0; rr < 2; rr++) {
            int m = bm + wm + mi * 16 + eg + rr * 8;
            if (m >= M) continue;
#pragma unroll
            for (int nj = 0; nj < 2; nj++) {
                int c = bn + wn + nj * 8 + 2 * etg;
                float2 hv = *reinterpret_cast<const float2*>(hin + (size_t)m * 256 + c);
                float o01[2];
#pragma unroll
                for (int j = 0; j < 2; j++) {
                    int q = rr * 2 + j;
                    float r = sigm(accR[mi][nj][q] + brz[nj][j]);
                    float z = sigm(accZ[mi][nj][q] + bzz[nj][j]);
                    float gin = accI[mi][nj][q] + bin[nj][j];
                    float ghn = accH[mi][nj][q] + bhn[nj][j];
                    float nn = tanhf(gin + r * ghn);
                    float hj = j ? hv.y : hv.x;
                    o01[j] = (1.f - z) * nn + z * hj;
                }
                *reinterpret_cast<float2*>(hout + (size_t)m * 256 + c) =
                    make_float2(o01[0], o01[1]);
                hbfout[(size_t)m * 128 + (c >> 1)] = pk(o01[0], o01[1]);
            }
        }
    }
}

// ---------------- pooling + classifier ----------------
__global__ void k_pool(const float* __restrict__ h, float* __restrict__ pooled, int M) {
    int c = threadIdx.x;
    int r0 = blockIdx.x * 256;
    int rend = min(r0 + 256, M);
    float s = 0.f;
    for (int r = r0; r < rend; r++) s += h[(size_t)r * 256 + c];
    atomicAdd(&pooled[c], s);
}

__global__ void k_final(const float* __restrict__ pooled, const float* __restrict__ Wc,
                        const float* __restrict__ bc, float* __restrict__ out) {
    __shared__ float red[256];
    int t = threadIdx.x;
    red[t] = pooled[t] * Wc[t];
    __syncthreads();
    for (int s = 128; s > 0; s >>= 1) {
        if (t < s) red[t] += red[t + s];
        __syncthreads();
    }
    if (t == 0) out[0] = 1.f / (1.f + expf(-(red[0] + bc[0])));
}

// ---------------- launch ----------------
extern "C" void kernel_launch(void* const* d_in, const int* in_sizes, int n_in,
                              void* d_out, int out_size) {
    const float* features = (const float*)d_in[0];
    const int* esrc = (const int*)d_in[1];
    const int* edst = (const int*)d_in[2];
    const int* etyp = (const int*)d_in[3];
    const float* W   = (const float*)d_in[4];
    const float* b   = (const float*)d_in[5];
    const float* Wih = (const float*)d_in[6];
    const float* Whh = (const float*)d_in[7];
    const float* bih = (const float*)d_in[8];
    const float* bhh = (const float*)d_in[9];
    const float* Wc  = (const float*)d_in[10];
    const float* bc  = (const float*)d_in[11];
    float* out = (float*)d_out;

    const int M = in_sizes[0] / DIN;   // 50000
    const int E = in_sizes[1];         // 800000
    const int np = M * 4;              // 200000 (dst,type) buckets

    unsigned *Sw, *hbfA, *hbfB, *aggw;
    float *hA, *hB, *cnt, *WT, *pooled;
    int *icnt, *cur, *off, *bsum, *ss;
    cudaGetSymbolAddress((void**)&Sw, d_Sw);
    cudaGetSymbolAddress((void**)&hA, d_hA);
    cudaGetSymbolAddress((void**)&hB, d_hB);
    cudaGetSymbolAddress((void**)&hbfA, d_hbfA);
    cudaGetSymbolAddress((void**)&hbfB, d_hbfB);
    cudaGetSymbolAddress((void**)&aggw, d_aggw);
    cudaGetSymbolAddress((void**)&cnt, d_cnt);
    cudaGetSymbolAddress((void**)&WT, d_WT);
    cudaGetSymbolAddress((void**)&pooled, d_pooled);
    cudaGetSymbolAddress((void**)&icnt, d_icnt);
    cudaGetSymbolAddress((void**)&cur, d_cur);
    cudaGetSymbolAddress((void**)&off, d_off);
    cudaGetSymbolAddress((void**)&bsum, d_bsum);
    cudaGetSymbolAddress((void**)&ss, d_ss);

    // ---- one-time (per launch) setup: CSR build + h0 + WT ----
    const int nb = (np + 1023) / 1024;
    k_zero<<<(np / 4 + 255) / 256, 256>>>((float4*)icnt, np / 4);
    k_zero<<<(np / 4 + 255) / 256, 256>>>((float4*)cur, np / 4);
    k_count_int<<<(E + 255) / 256, 256>>>(edst, etyp, icnt, E);
    k_cnt2float<<<(np + 255) / 256, 256>>>(icnt, cnt, np);
    k_scan1<<<nb, 256>>>(icnt, off, bsum, np);
    k_scan2<<<1, 256>>>(bsum, nb);
    k_scan3<<<nb, 256>>>(off, bsum, np, E);
    k_place<<<(E + 255) / 256, 256>>>(esrc, edst, etyp, off, cur, ss, E);
    k_init_h<<<((size_t)M * 128 + 255) / 256, 256>>>(features, hA, hbfA, M);
    k_transpose<<<(256 * 1024 + 255) / 256, 256>>>(W, WT);

    float* hin = hA;  float* hout = hB;
    unsigned* hbfin = hbfA;  unsigned* hbfout = hbfB;
    const int mb = (M + 127) / 128;
    dim3 gAgg(2, mb), gGates(4, mb);
    const int gGather = (np + 7) / 8;

    for (int step = 0; step < 8; step++) {
        k_gather<<<gGather, 256>>>(hbfin, ss, off, Sw, np);
        gemm_agg<<<gAgg, 256>>>(Sw, WT, aggw, M, cnt, b);
        k_gates<<<gGates, 256>>>(aggw, hbfin, hin, Wih, Whh, bih, bhh, hout, hbfout, M);
        float* t = hin; hin = hout; hout = t;
        unsigned* tw = hbfin; hbfin = hbfout; hbfout = tw;
    }

    k_zero<<<1, 64>>>((float4*)pooled, 64);
    k_pool<<<(M + 255) / 256, 256>>>(hin, pooled, M);
    k_final<<<1, 256>>>(pooled, Wc, bc, out);
}

// round 16
// speedup vs baseline: 4.4246x; 1.3444x over previous
#include <cuda_runtime.h>
#include <cuda_bf16.h>
#include <math.h>

#define NMAX 50000
#define EMAX 800000
#define D 256
#define DIN 128

// ---------------- scratch (static device globals; no allocation) ----------------
__device__ unsigned d_Sw[(size_t)NMAX * 512];    // [N*4 buckets][128 words] bf16x2 neighbor sums
__device__ float d_hA[(size_t)NMAX * D];
__device__ float d_hB[(size_t)NMAX * D];
__device__ unsigned d_hbfA[(size_t)NMAX * 128];  // bf16x2 packed h (ping)
__device__ unsigned d_hbfB[(size_t)NMAX * 128];  // bf16x2 packed h (pong)
__device__ unsigned d_aggw[(size_t)NMAX * 128];  // bf16x2 packed agg
__device__ float d_cnt[(size_t)NMAX * 4];
__device__ unsigned d_WTw[(size_t)D * 512];      // bf16x2 packed Wstack^T: [256 out][512 kwords]
__device__ unsigned d_Wihw[(size_t)768 * 128];   // bf16x2 packed W_ih: [768][128 kwords]
__device__ unsigned d_Whhw[(size_t)768 * 128];   // bf16x2 packed W_hh
__device__ float d_pooled[D];
// CSR build
__device__ int d_icnt[(size_t)NMAX * 4];
__device__ int d_cur[(size_t)NMAX * 4];
__device__ int d_off[(size_t)NMAX * 4 + 1];
__device__ int d_bsum[256];
__device__ int d_ss[EMAX];

// ---------------- bf16 / mma helpers ----------------
__device__ __forceinline__ unsigned pk(float lo, float hi) {
    __nv_bfloat162 t = __floats2bfloat162_rn(lo, hi);
    return *reinterpret_cast<unsigned*>(&t);
}

__device__ __forceinline__ float2 upk(unsigned u) {
    __nv_bfloat162 t = *reinterpret_cast<__nv_bfloat162*>(&u);
    return __bfloat1622float2(t);
}

__device__ __forceinline__ void mma_bf16(float* d, const unsigned* a, const unsigned* b) {
    asm volatile(
        "mma.sync.aligned.m16n8k16.row.col.f32.bf16.bf16.f32 "
        "{%0,%1,%2,%3}, {%4,%5,%6,%7}, {%8,%9}, {%0,%1,%2,%3};\n"
        : "+f"(d[0]), "+f"(d[1]), "+f"(d[2]), "+f"(d[3])
        : "r"(a[0]), "r"(a[1]), "r"(a[2]), "r"(a[3]), "r"(b[0]), "r"(b[1]));
}

__device__ __forceinline__ void ldsm_x4(unsigned& r0, unsigned& r1, unsigned& r2,
                                        unsigned& r3, unsigned addr) {
    asm volatile("ldmatrix.sync.aligned.m8n8.x4.shared.b16 {%0,%1,%2,%3}, [%4];"
                 : "=r"(r0), "=r"(r1), "=r"(r2), "=r"(r3) : "r"(addr));
}

__device__ __forceinline__ void cp16(unsigned dst, const void* src) {
    asm volatile("cp.async.cg.shared.global [%0], [%1], 16;"
                 :: "r"(dst), "l"(src) : "memory");
}

__device__ __forceinline__ float sigm(float x) { return 1.f / (1.f + expf(-x)); }

// swizzled byte offset for (row, 16B-half) in a row-major 32B-row tile
__device__ __forceinline__ unsigned sw_off(int row, int chunk) {
    return (unsigned)(row * 32 + ((chunk ^ ((row >> 2) & 1)) * 16));
}

// ---------------- setup helpers ----------------
__global__ void k_zero(float4* __restrict__ p, int n4) {
    int i = blockIdx.x * blockDim.x + threadIdx.x;
    if (i < n4) p[i] = make_float4(0.f, 0.f, 0.f, 0.f);
}

__global__ void k_count_int(const int* __restrict__ dst, const int* __restrict__ typ,
                            int* __restrict__ icnt, int e) {
    int i = blockIdx.x * blockDim.x + threadIdx.x;
    if (i < e) atomicAdd(&icnt[(size_t)dst[i] * 4 + typ[i]], 1);
}

__global__ void k_cnt2float(const int* __restrict__ icnt, float* __restrict__ cnt, int np) {
    int i = blockIdx.x * blockDim.x + threadIdx.x;
    if (i < np) cnt[i] = (float)icnt[i];
}

__global__ void k_scan1(const int* __restrict__ in, int* __restrict__ out,
                        int* __restrict__ bsum, int np) {
    __shared__ int sh[256];
    int t = threadIdx.x;
    int base = blockIdx.x * 1024 + t * 4;
    int v0 = (base + 0 < np) ? in[base + 0] : 0;
    int v1 = (base + 1 < np) ? in[base + 1] : 0;
    int v2 = (base + 2 < np) ? in[base + 2] : 0;
    int v3 = (base + 3 < np) ? in[base + 3] : 0;
    int s = v0 + v1 + v2 + v3;
    sh[t] = s;
    __syncthreads();
    for (int ofs = 1; ofs < 256; ofs <<= 1) {
        int x = (t >= ofs) ? sh[t - ofs] : 0;
        __syncthreads();
        sh[t] += x;
        __syncthreads();
    }
    int ex = sh[t] - s;
    if (base + 0 < np) out[base + 0] = ex;
    if (base + 1 < np) out[base + 1] = ex + v0;
    if (base + 2 < np) out[base + 2] = ex + v0 + v1;
    if (base + 3 < np) out[base + 3] = ex + v0 + v1 + v2;
    if (t == 255) bsum[blockIdx.x] = sh[255];
}

__global__ void k_scan2(int* __restrict__ bsum, int nb) {
    __shared__ int sh[256];
    int t = threadIdx.x;
    int v = (t < nb) ? bsum[t] : 0;
    sh[t] = v;
    __syncthreads();
    for (int ofs = 1; ofs < 256; ofs <<= 1) {
        int x = (t >= ofs) ? sh[t - ofs] : 0;
        __syncthreads();
        sh[t] += x;
        __syncthreads();
    }
    if (t < nb) bsum[t] = sh[t] - v;
}

__global__ void k_scan3(int* __restrict__ off, const int* __restrict__ bsum,
                        int np, int total) {
    int add = bsum[blockIdx.x];
    int base = blockIdx.x * 1024 + threadIdx.x * 4;
#pragma unroll
    for (int j = 0; j < 4; j++)
        if (base + j < np) off[base + j] += add;
    if (blockIdx.x == 0 && threadIdx.x == 0) off[np] = total;
}

__global__ void k_place(const int* __restrict__ src, const int* __restrict__ dst,
                        const int* __restrict__ typ, const int* __restrict__ off,
                        int* __restrict__ cur, int* __restrict__ ss, int e) {
    int i = blockIdx.x * blockDim.x + threadIdx.x;
    if (i >= e) return;
    int p = dst[i] * 4 + typ[i];
    int pos = off[p] + atomicAdd(&cur[p], 1);
    ss[pos] = src[i];
}

__global__ void k_init_h(const float* __restrict__ f, float* __restrict__ h,
                         unsigned* __restrict__ hbf, int n) {
    int i = blockIdx.x * blockDim.x + threadIdx.x;
    int m = i >> 7, cp = i & 127;
    if (m >= n) return;
    float v0 = (cp < 64) ? f[(size_t)m * DIN + 2 * cp] : 0.f;
    float v1 = (cp < 64) ? f[(size_t)m * DIN + 2 * cp + 1] : 0.f;
    h[(size_t)m * 256 + 2 * cp] = v0;
    h[(size_t)m * 256 + 2 * cp + 1] = v1;
    hbf[(size_t)m * 128 + cp] = pk(v0, v1);
}

// WTw[e][w] = pack(Wstack[2w][e], Wstack[2w+1][e]); Wstack = W viewed [1024,256]
__global__ void k_transpose_pack(const float* __restrict__ W, unsigned* __restrict__ WTw) {
    int i = blockIdx.x * blockDim.x + threadIdx.x;
    if (i >= 256 * 512) return;
    int e = i >> 9, w = i & 511;
    WTw[i] = pk(W[(size_t)(2 * w) * 256 + e], W[(size_t)(2 * w + 1) * 256 + e]);
}

// pack [768,256] fp32 row-major -> [768][128] bf16x2 words
__global__ void k_pack768(const float* __restrict__ Wsrc, unsigned* __restrict__ Wdst) {
    int i = blockIdx.x * blockDim.x + threadIdx.x;
    if (i >= 768 * 128) return;
    int r = i >> 7, w = i & 127;
    Wdst[i] = pk(Wsrc[(size_t)r * 256 + 2 * w], Wsrc[(size_t)r * 256 + 2 * w + 1]);
}

// ---------------- CSR gather (bf16 h) ----------------
__global__ void k_gather(const unsigned* __restrict__ hbf, const int* __restrict__ ss,
                         const int* __restrict__ off, unsigned* __restrict__ Sw, int np) {
    int p = blockIdx.x * 8 + (threadIdx.x >> 5);
    if (p >= np) return;
    int lane = threadIdx.x & 31;
    int beg = __ldg(off + p), end = __ldg(off + p + 1);
    float a0 = 0.f, a1 = 0.f, a2 = 0.f, a3 = 0.f, a4 = 0.f, a5 = 0.f, a6 = 0.f, a7 = 0.f;
    for (int e = beg; e < end; e++) {
        uint4 w = __ldg((const uint4*)(hbf + (size_t)__ldg(ss + e) * 128 + lane * 4));
        float2 f0 = upk(w.x), f1 = upk(w.y), f2 = upk(w.z), f3 = upk(w.w);
        a0 += f0.x; a1 += f0.y; a2 += f1.x; a3 += f1.y;
        a4 += f2.x; a5 += f2.y; a6 += f3.x; a7 += f3.y;
    }
    uint4 o;
    o.x = pk(a0, a1); o.y = pk(a2, a3); o.z = pk(a4, a5); o.w = pk(a6, a7);
    *reinterpret_cast<uint4*>(Sw + (size_t)p * 128 + lane * 4) = o;
}

// ---------------- agg GEMM (cp.async + ldmatrix + mma.sync) ----------------
// aggw = bf16( Sw[M,1024] @ WTw^T + cnt-weighted bias )
__global__ __launch_bounds__(256) void gemm_agg(
    const unsigned* __restrict__ Aw, const unsigned* __restrict__ Bw,
    unsigned* __restrict__ Cw, int M,
    const float* __restrict__ cnt, const float* __restrict__ bias)
{
    __shared__ unsigned As[2][1024];   // 128 rows x 8 words (32B rows, swizzled)
    __shared__ unsigned Bs[2][1024];
    const int tid = threadIdx.x;
    const int bm = blockIdx.y * 128;
    const int bn = blockIdx.x * 128;
    const int row = tid >> 1, half = tid & 1;
    int arow = bm + row; if (arow >= M) arow = M - 1;     // clamp; garbage rows discarded
    const unsigned* Agp = Aw + (size_t)arow * 512 + half * 4;
    const unsigned* Bgp = Bw + (size_t)(bn + row) * 512 + half * 4;

    const unsigned sAb = (unsigned)__cvta_generic_to_shared(&As[0][0]);
    const unsigned sBb = (unsigned)__cvta_generic_to_shared(&Bs[0][0]);
    const unsigned dOff = sw_off(row, half);

    // prologue: chunk 0 -> buf 0
    cp16(sAb + dOff, Agp);
    cp16(sBb + dOff, Bgp);
    asm volatile("cp.async.commit_group;" ::: "memory");

    const int wid = tid >> 5, lane = tid & 31;
    const int wm = (wid & 1) * 64;
    const int wn = (wid >> 1) * 32;
    const int lrow = (lane & 7) + ((lane >> 3) & 1) * 8;
    const int lc = (lane >> 4) & 1;
    unsigned aoff[4], boff[2];
#pragma unroll
    for (int mi = 0; mi < 4; mi++) aoff[mi] = sw_off(wm + mi * 16 + lrow, lc);
#pragma unroll
    for (int nt = 0; nt < 2; nt++) boff[nt] = sw_off(wn + nt * 16 + lrow, lc);

    float acc[4][4][4];
#pragma unroll
    for (int i = 0; i < 4; i++)
#pragma unroll
        for (int j = 0; j < 4; j++)
#pragma unroll
            for (int q = 0; q < 4; q++) acc[i][j][q] = 0.f;

    int buf = 0;
    for (int c = 0; c < 64; c++) {
        const bool more = (c < 63);
        if (more) {
            unsigned d2 = dOff + (buf ^ 1) * 4096;
            cp16(sAb + d2, Agp + (c + 1) * 8);
            cp16(sBb + d2, Bgp + (c + 1) * 8);
            asm volatile("cp.async.commit_group;" ::: "memory");
            asm volatile("cp.async.wait_group 1;" ::: "memory");
        } else {
            asm volatile("cp.async.wait_group 0;" ::: "memory");
        }
        __syncthreads();
        {
            const unsigned ab = sAb + buf * 4096;
            const unsigned bb = sBb + buf * 4096;
            unsigned af[4][4], bfr[4][2];
#pragma unroll
            for (int mi = 0; mi < 4; mi++)
                ldsm_x4(af[mi][0], af[mi][1], af[mi][2], af[mi][3], ab + aoff[mi]);
#pragma unroll
            for (int nt = 0; nt < 2; nt++) {
                unsigned r0, r1, r2, r3;
                ldsm_x4(r0, r1, r2, r3, bb + boff[nt]);
                bfr[nt * 2 + 0][0] = r0; bfr[nt * 2 + 0][1] = r2;
                bfr[nt * 2 + 1][0] = r1; bfr[nt * 2 + 1][1] = r3;
            }
#pragma unroll
            for (int mi = 0; mi < 4; mi++)
#pragma unroll
                for (int nj = 0; nj < 4; nj++)
                    mma_bf16(acc[mi][nj], af[mi], bfr[nj]);
        }
        __syncthreads();
        buf ^= 1;
    }

    // epilogue: +sum_t cnt[m,t]*bias[t,n], pack to bf16x2
    const int eg = lane >> 2, etg = lane & 3;
#pragma unroll
    for (int mi = 0; mi < 4; mi++) {
#pragma unroll
        for (int rr = 0; rr < 2; rr++) {
            int m = bm + wm + mi * 16 + eg + rr * 8;
            if (m >= M) continue;
            float4 c4 = *reinterpret_cast<const float4*>(cnt + (size_t)m * 4);
            unsigned* Cr = Cw + (size_t)m * 128;
#pragma unroll
            for (int nj = 0; nj < 4; nj++) {
                int c = bn + wn + nj * 8 + 2 * etg;
                float add0 = c4.x * __ldg(bias + 0 * 256 + c) + c4.y * __ldg(bias + 1 * 256 + c)
                           + c4.z * __ldg(bias + 2 * 256 + c) + c4.w * __ldg(bias + 3 * 256 + c);
                float add1 = c4.x * __ldg(bias + 0 * 256 + c + 1) + c4.y * __ldg(bias + 1 * 256 + c + 1)
                           + c4.z * __ldg(bias + 2 * 256 + c + 1) + c4.w * __ldg(bias + 3 * 256 + c + 1);
                Cr[c >> 1] = pk(acc[mi][nj][rr * 2 + 0] + add0,
                                acc[mi][nj][rr * 2 + 1] + add1);
            }
        }
    }
}

// ---------------- fused gates GEMM + GRU (cp.async + ldmatrix + mma.sync) ----------------
__global__ __launch_bounds__(256) void k_gates(
    const unsigned* __restrict__ aggw, const unsigned* __restrict__ hbfw,
    const float* __restrict__ hin,
    const unsigned* __restrict__ Wihw, const unsigned* __restrict__ Whhw,
    const float* __restrict__ bih, const float* __restrict__ bhh,
    float* __restrict__ hout, unsigned* __restrict__ hbfout, int M)
{
    __shared__ unsigned Aa[2][1024];    // 128 rows x 8 words
    __shared__ unsigned Ah[2][1024];
    __shared__ unsigned Bsx[2][3072];   // 384 rows (6 panels x 64) x 8 words
    const int tid = threadIdx.x;
    const int bm = blockIdx.y * 128;
    const int bn = blockIdx.x * 64;

    // A staging: row = tid>>1, half = tid&1
    const int row = tid >> 1, half = tid & 1;
    int arow = bm + row; if (arow >= M) arow = M - 1;     // garbage rows discarded
    const unsigned* Agp = aggw + (size_t)arow * 128 + half * 4;
    const unsigned* Hgp = hbfw + (size_t)arow * 128 + half * 4;
    const unsigned dAOff = sw_off(row, half);

    // B staging: 3 transfers per thread; idx = j*256 + tid -> R = idx>>1 (0..383), hB = idx&1
    const unsigned* Bgp[3];
    unsigned dBOff[3];
#pragma unroll
    for (int j = 0; j < 3; j++) {
        int idx = j * 256 + tid;
        int R = idx >> 1, hB = idx & 1;
        int p = R >> 6, n = R & 63;
        const unsigned* base = (p < 3) ? (Wihw + (size_t)(p * 256 + bn + n) * 128)
                                       : (Whhw + (size_t)((p - 3) * 256 + bn + n) * 128);
        Bgp[j] = base + hB * 4;
        dBOff[j] = sw_off(R, hB);
    }

    const unsigned sAab = (unsigned)__cvta_generic_to_shared(&Aa[0][0]);
    const unsigned sAhb = (unsigned)__cvta_generic_to_shared(&Ah[0][0]);
    const unsigned sBxb = (unsigned)__cvta_generic_to_shared(&Bsx[0][0]);

    // prologue: chunk 0 -> buf 0
    cp16(sAab + dAOff, Agp);
    cp16(sAhb + dAOff, Hgp);
#pragma unroll
    for (int j = 0; j < 3; j++) cp16(sBxb + dBOff[j], Bgp[j]);
    asm volatile("cp.async.commit_group;" ::: "memory");

    const int wid = tid >> 5, lane = tid & 31;
    const int wm = (wid & 1) * 64;
    const int wn = (wid >> 1) * 16;
    const int lrow = (lane & 7) + ((lane >> 3) & 1) * 8;
    const int lc = (lane >> 4) & 1;
    unsigned aoff[4], bpoff[6];
#pragma unroll
    for (int mi = 0; mi < 4; mi++) aoff[mi] = sw_off(wm + mi * 16 + lrow, lc);
#pragma unroll
    for (int p = 0; p < 6; p++) bpoff[p] = sw_off(p * 64 + wn + lrow, lc);

    float accR[4][2][4], accZ[4][2][4], accI[4][2][4], accH[4][2][4];
#pragma unroll
    for (int i = 0; i < 4; i++)
#pragma unroll
        for (int j = 0; j < 2; j++)
#pragma unroll
            for (int q = 0; q < 4; q++) {
                accR[i][j][q] = 0.f; accZ[i][j][q] = 0.f;
                accI[i][j][q] = 0.f; accH[i][j][q] = 0.f;
            }

    int buf = 0;
    for (int c = 0; c < 16; c++) {
        const bool more = (c < 15);
        if (more) {
            unsigned dA2 = dAOff + (buf ^ 1) * 4096;
            cp16(sAab + dA2, Agp + (c + 1) * 8);
            cp16(sAhb + dA2, Hgp + (c + 1) * 8);
#pragma unroll
            for (int j = 0; j < 3; j++)
                cp16(sBxb + dBOff[j] + (buf ^ 1) * 12288, Bgp[j] + (c + 1) * 8);
            asm volatile("cp.async.commit_group;" ::: "memory");
            asm volatile("cp.async.wait_group 1;" ::: "memory");
        } else {
            asm volatile("cp.async.wait_group 0;" ::: "memory");
        }
        __syncthreads();
        {
            const unsigned ab = sAab + buf * 4096;
            const unsigned hb = sAhb + buf * 4096;
            const unsigned bb = sBxb + buf * 12288;
            unsigned afa[4][4], afh[4][4], bfr[6][2][2];
#pragma unroll
            for (int mi = 0; mi < 4; mi++) {
                ldsm_x4(afa[mi][0], afa[mi][1], afa[mi][2], afa[mi][3], ab + aoff[mi]);
                ldsm_x4(afh[mi][0], afh[mi][1], afh[mi][2], afh[mi][3], hb + aoff[mi]);
            }
#pragma unroll
            for (int p = 0; p < 6; p++) {
                unsigned r0, r1, r2, r3;
                ldsm_x4(r0, r1, r2, r3, bb + bpoff[p]);
                bfr[p][0][0] = r0; bfr[p][0][1] = r2;
                bfr[p][1][0] = r1; bfr[p][1][1] = r3;
            }
#pragma unroll
            for (int mi = 0; mi < 4; mi++)
#pragma unroll
                for (int nj = 0; nj < 2; nj++) {
                    mma_bf16(accR[mi][nj], afa[mi], bfr[0][nj]);
                    mma_bf16(accR[mi][nj], afh[mi], bfr[3][nj]);
                    mma_bf16(accZ[mi][nj], afa[mi], bfr[1][nj]);
                    mma_bf16(accZ[mi][nj], afh[mi], bfr[4][nj]);
                    mma_bf16(accI[mi][nj], afa[mi], bfr[2][nj]);
                    mma_bf16(accH[mi][nj], afh[mi], bfr[5][nj]);
                }
        }
        __syncthreads();
        buf ^= 1;
    }

    // GRU epilogue
    const int eg = lane >> 2, etg = lane & 3;
    float brz[2][2], bzz[2][2], bin[2][2], bhn[2][2];
#pragma unroll
    for (int nj = 0; nj < 2; nj++)
#pragma unroll
        for (int j = 0; j < 2; j++) {
            int cc = bn + wn + nj * 8 + 2 * etg + j;
            brz[nj][j] = __ldg(bih + cc) + __ldg(bhh + cc);
            bzz[nj][j] = __ldg(bih + 256 + cc) + __ldg(bhh + 256 + cc);
            bin[nj][j] = __ldg(bih + 512 + cc);
            bhn[nj][j] = __ldg(bhh + 512 + cc);
        }

#pragma unroll
    for (int mi = 0; mi < 4; mi++) {
#pragma unroll
        for (int rr = 0; rr < 2; rr++) {
            int m = bm + wm + mi * 16 + eg + rr * 8;
            if (m >= M) continue;
#pragma unroll
            for (int nj = 0; nj < 2; nj++) {
                int c = bn + wn + nj * 8 + 2 * etg;
                float2 hv = *reinterpret_cast<const float2*>(hin + (size_t)m * 256 + c);
                float o01[2];
#pragma unroll
                for (int j = 0; j < 2; j++) {
                    int q = rr * 2 + j;
                    float r = sigm(accR[mi][nj][q] + brz[nj][j]);
                    float z = sigm(accZ[mi][nj][q] + bzz[nj][j]);
                    float gin = accI[mi][nj][q] + bin[nj][j];
                    float ghn = accH[mi][nj][q] + bhn[nj][j];
                    float nn = tanhf(gin + r * ghn);
                    float hj = j ? hv.y : hv.x;
                    o01[j] = (1.f - z) * nn + z * hj;
                }
                *reinterpret_cast<float2*>(hout + (size_t)m * 256 + c) =
                    make_float2(o01[0], o01[1]);
                hbfout[(size_t)m * 128 + (c >> 1)] = pk(o01[0], o01[1]);
            }
        }
    }
}

// ---------------- pooling + classifier ----------------
__global__ void k_pool(const float* __restrict__ h, float* __restrict__ pooled, int M) {
    int c = threadIdx.x;
    int r0 = blockIdx.x * 256;
    int rend = min(r0 + 256, M);
    float s = 0.f;
    for (int r = r0; r < rend; r++) s += h[(size_t)r * 256 + c];
    atomicAdd(&pooled[c], s);
}

__global__ void k_final(const float* __restrict__ pooled, const float* __restrict__ Wc,
                        const float* __restrict__ bc, float* __restrict__ out) {
    __shared__ float red[256];
    int t = threadIdx.x;
    red[t] = pooled[t] * Wc[t];
    __syncthreads();
    for (int s = 128; s > 0; s >>= 1) {
        if (t < s) red[t] += red[t + s];
        __syncthreads();
    }
    if (t == 0) out[0] = 1.f / (1.f + expf(-(red[0] + bc[0])));
}

// ---------------- launch ----------------
extern "C" void kernel_launch(void* const* d_in, const int* in_sizes, int n_in,
                              void* d_out, int out_size) {
    const float* features = (const float*)d_in[0];
    const int* esrc = (const int*)d_in[1];
    const int* edst = (const int*)d_in[2];
    const int* etyp = (const int*)d_in[3];
    const float* W   = (const float*)d_in[4];
    const float* b   = (const float*)d_in[5];
    const float* Wih = (const float*)d_in[6];
    const float* Whh = (const float*)d_in[7];
    const float* bih = (const float*)d_in[8];
    const float* bhh = (const float*)d_in[9];
    const float* Wc  = (const float*)d_in[10];
    const float* bc  = (const float*)d_in[11];
    float* out = (float*)d_out;

    const int M = in_sizes[0] / DIN;   // 50000
    const int E = in_sizes[1];         // 800000
    const int np = M * 4;              // 200000 (dst,type) buckets

    unsigned *Sw, *hbfA, *hbfB, *aggw, *WTw, *Wihw, *Whhw;
    float *hA, *hB, *cnt, *pooled;
    int *icnt, *cur, *off, *bsum, *ss;
    cudaGetSymbolAddress((void**)&Sw, d_Sw);
    cudaGetSymbolAddress((void**)&hA, d_hA);
    cudaGetSymbolAddress((void**)&hB, d_hB);
    cudaGetSymbolAddress((void**)&hbfA, d_hbfA);
    cudaGetSymbolAddress((void**)&hbfB, d_hbfB);
    cudaGetSymbolAddress((void**)&aggw, d_aggw);
    cudaGetSymbolAddress((void**)&cnt, d_cnt);
    cudaGetSymbolAddress((void**)&WTw, d_WTw);
    cudaGetSymbolAddress((void**)&Wihw, d_Wihw);
    cudaGetSymbolAddress((void**)&Whhw, d_Whhw);
    cudaGetSymbolAddress((void**)&pooled, d_pooled);
    cudaGetSymbolAddress((void**)&icnt, d_icnt);
    cudaGetSymbolAddress((void**)&cur, d_cur);
    cudaGetSymbolAddress((void**)&off, d_off);
    cudaGetSymbolAddress((void**)&bsum, d_bsum);
    cudaGetSymbolAddress((void**)&ss, d_ss);

    // ---- one-time (per launch) setup: CSR build + h0 + packed weights ----
    const int nb = (np + 1023) / 1024;
    k_zero<<<(np / 4 + 255) / 256, 256>>>((float4*)icnt, np / 4);
    k_zero<<<(np / 4 + 255) / 256, 256>>>((float4*)cur, np / 4);
    k_count_int<<<(E + 255) / 256, 256>>>(edst, etyp, icnt, E);
    k_cnt2float<<<(np + 255) / 256, 256>>>(icnt, cnt, np);
    k_scan1<<<nb, 256>>>(icnt, off, bsum, np);
    k_scan2<<<1, 256>>>(bsum, nb);
    k_scan3<<<nb, 256>>>(off, bsum, np, E);
    k_place<<<(E + 255) / 256, 256>>>(esrc, edst, etyp, off, cur, ss, E);
    k_init_h<<<((size_t)M * 128 + 255) / 256, 256>>>(features, hA, hbfA, M);
    k_transpose_pack<<<(256 * 512 + 255) / 256, 256>>>(W, WTw);
    k_pack768<<<(768 * 128 + 255) / 256, 256>>>(Wih, Wihw);
    k_pack768<<<(768 * 128 + 255) / 256, 256>>>(Whh, Whhw);

    float* hin = hA;  float* hout = hB;
    unsigned* hbfin = hbfA;  unsigned* hbfout = hbfB;
    const int mb = (M + 127) / 128;
    dim3 gAgg(2, mb), gGates(4, mb);
    const int gGather = (np + 7) / 8;

    for (int step = 0; step < 8; step++) {
        k_gather<<<gGather, 256>>>(hbfin, ss, off, Sw, np);
        gemm_agg<<<gAgg, 256>>>(Sw, WTw, aggw, M, cnt, b);
        k_gates<<<gGates, 256>>>(aggw, hbfin, hin, Wihw, Whhw, bih, bhh, hout, hbfout, M);
        float* t = hin; hin = hout; hout = t;
        unsigned* tw = hbfin; hbfin = hbfout; hbfout = tw;
    }

    k_zero<<<1, 64>>>((float4*)pooled, 64);
    k_pool<<<(M + 255) / 256, 256>>>(hin, pooled, M);
    k_final<<<1, 256>>>(pooled, Wc, bc, out);
}

// round 17
// speedup vs baseline: 4.6287x; 1.0461x over previous
#include <cuda_runtime.h>
#include <cuda_bf16.h>
#include <math.h>

#define NMAX 50000
#define EMAX 800000
#define D 256
#define DIN 128

// ---------------- scratch (static device globals; no allocation) ----------------
__device__ unsigned d_Sw[(size_t)NMAX * 512];    // [N*4 buckets][128 words] bf16x2 neighbor sums
__device__ float d_hA[(size_t)NMAX * D];
__device__ float d_hB[(size_t)NMAX * D];
__device__ unsigned d_hbfA[(size_t)NMAX * 128];  // bf16x2 packed h (ping)
__device__ unsigned d_hbfB[(size_t)NMAX * 128];  // bf16x2 packed h (pong)
__device__ unsigned d_aggw[(size_t)NMAX * 128];  // bf16x2 packed agg
__device__ float d_cnt[(size_t)NMAX * 4];
__device__ unsigned d_WTw[(size_t)D * 512];      // bf16x2 packed Wstack^T: [256 out][512 kwords]
__device__ unsigned d_Wihw[(size_t)768 * 128];   // bf16x2 packed W_ih: [768][128 kwords]
__device__ unsigned d_Whhw[(size_t)768 * 128];   // bf16x2 packed W_hh
__device__ float d_pooled[D];
// CSR build
__device__ int d_icnt[(size_t)NMAX * 4];
__device__ int d_cur[(size_t)NMAX * 4];
__device__ int d_off[(size_t)NMAX * 4 + 1];
__device__ int d_bsum[256];
__device__ int d_ss[EMAX];

// ---------------- bf16 / mma helpers ----------------
__device__ __forceinline__ unsigned pk(float lo, float hi) {
    __nv_bfloat162 t = __floats2bfloat162_rn(lo, hi);
    return *reinterpret_cast<unsigned*>(&t);
}

__device__ __forceinline__ float2 upk(unsigned u) {
    __nv_bfloat162 t = *reinterpret_cast<__nv_bfloat162*>(&u);
    return __bfloat1622float2(t);
}

__device__ __forceinline__ void mma_bf16(float* d, const unsigned* a, const unsigned* b) {
    asm volatile(
        "mma.sync.aligned.m16n8k16.row.col.f32.bf16.bf16.f32 "
        "{%0,%1,%2,%3}, {%4,%5,%6,%7}, {%8,%9}, {%0,%1,%2,%3};\n"
        : "+f"(d[0]), "+f"(d[1]), "+f"(d[2]), "+f"(d[3])
        : "r"(a[0]), "r"(a[1]), "r"(a[2]), "r"(a[3]), "r"(b[0]), "r"(b[1]));
}

__device__ __forceinline__ void ldsm_x4(unsigned& r0, unsigned& r1, unsigned& r2,
                                        unsigned& r3, unsigned addr) {
    asm volatile("ldmatrix.sync.aligned.m8n8.x4.shared.b16 {%0,%1,%2,%3}, [%4];"
                 : "=r"(r0), "=r"(r1), "=r"(r2), "=r"(r3) : "r"(addr));
}

__device__ __forceinline__ void cp16(unsigned dst, const void* src) {
    asm volatile("cp.async.cg.shared.global [%0], [%1], 16;"
                 :: "r"(dst), "l"(src) : "memory");
}

__device__ __forceinline__ float sigm(float x) { return 1.f / (1.f + expf(-x)); }

// swizzled byte offset for (row, 16B-chunk) in a 32B-row tile (k=16 tiles)
__device__ __forceinline__ unsigned sw_off(int row, int chunk) {
    return (unsigned)(row * 32 + ((chunk ^ ((row >> 2) & 1)) * 16));
}
// swizzled byte offset for (row, 16B-chunk 0..3) in a 64B-row tile (k=32 tiles)
__device__ __forceinline__ unsigned sw32(int row, int chunk) {
    return (unsigned)(row * 64 + ((chunk ^ ((row >> 1) & 3)) * 16));
}

// ---------------- setup helpers ----------------
__global__ void k_zero(float4* __restrict__ p, int n4) {
    int i = blockIdx.x * blockDim.x + threadIdx.x;
    if (i < n4) p[i] = make_float4(0.f, 0.f, 0.f, 0.f);
}

__global__ void k_count_int(const int* __restrict__ dst, const int* __restrict__ typ,
                            int* __restrict__ icnt, int e) {
    int i = blockIdx.x * blockDim.x + threadIdx.x;
    if (i < e) atomicAdd(&icnt[(size_t)dst[i] * 4 + typ[i]], 1);
}

__global__ void k_cnt2float(const int* __restrict__ icnt, float* __restrict__ cnt, int np) {
    int i = blockIdx.x * blockDim.x + threadIdx.x;
    if (i < np) cnt[i] = (float)icnt[i];
}

__global__ void k_scan1(const int* __restrict__ in, int* __restrict__ out,
                        int* __restrict__ bsum, int np) {
    __shared__ int sh[256];
    int t = threadIdx.x;
    int base = blockIdx.x * 1024 + t * 4;
    int v0 = (base + 0 < np) ? in[base + 0] : 0;
    int v1 = (base + 1 < np) ? in[base + 1] : 0;
    int v2 = (base + 2 < np) ? in[base + 2] : 0;
    int v3 = (base + 3 < np) ? in[base + 3] : 0;
    int s = v0 + v1 + v2 + v3;
    sh[t] = s;
    __syncthreads();
    for (int ofs = 1; ofs < 256; ofs <<= 1) {
        int x = (t >= ofs) ? sh[t - ofs] : 0;
        __syncthreads();
        sh[t] += x;
        __syncthreads();
    }
    int ex = sh[t] - s;
    if (base + 0 < np) out[base + 0] = ex;
    if (base + 1 < np) out[base + 1] = ex + v0;
    if (base + 2 < np) out[base + 2] = ex + v0 + v1;
    if (base + 3 < np) out[base + 3] = ex + v0 + v1 + v2;
    if (t == 255) bsum[blockIdx.x] = sh[255];
}

__global__ void k_scan2(int* __restrict__ bsum, int nb) {
    __shared__ int sh[256];
    int t = threadIdx.x;
    int v = (t < nb) ? bsum[t] : 0;
    sh[t] = v;
    __syncthreads();
    for (int ofs = 1; ofs < 256; ofs <<= 1) {
        int x = (t >= ofs) ? sh[t - ofs] : 0;
        __syncthreads();
        sh[t] += x;
        __syncthreads();
    }
    if (t < nb) bsum[t] = sh[t] - v;
}

__global__ void k_scan3(int* __restrict__ off, const int* __restrict__ bsum,
                        int np, int total) {
    int add = bsum[blockIdx.x];
    int base = blockIdx.x * 1024 + threadIdx.x * 4;
#pragma unroll
    for (int j = 0; j < 4; j++)
        if (base + j < np) off[base + j] += add;
    if (blockIdx.x == 0 && threadIdx.x == 0) off[np] = total;
}

__global__ void k_place(const int* __restrict__ src, const int* __restrict__ dst,
                        const int* __restrict__ typ, const int* __restrict__ off,
                        int* __restrict__ cur, int* __restrict__ ss, int e) {
    int i = blockIdx.x * blockDim.x + threadIdx.x;
    if (i >= e) return;
    int p = dst[i] * 4 + typ[i];
    int pos = off[p] + atomicAdd(&cur[p], 1);
    ss[pos] = src[i];
}

__global__ void k_init_h(const float* __restrict__ f, float* __restrict__ h,
                         unsigned* __restrict__ hbf, int n) {
    int i = blockIdx.x * blockDim.x + threadIdx.x;
    int m = i >> 7, cp = i & 127;
    if (m >= n) return;
    float v0 = (cp < 64) ? f[(size_t)m * DIN + 2 * cp] : 0.f;
    float v1 = (cp < 64) ? f[(size_t)m * DIN + 2 * cp + 1] : 0.f;
    h[(size_t)m * 256 + 2 * cp] = v0;
    h[(size_t)m * 256 + 2 * cp + 1] = v1;
    hbf[(size_t)m * 128 + cp] = pk(v0, v1);
}

// WTw[e][w] = pack(Wstack[2w][e], Wstack[2w+1][e]); Wstack = W viewed [1024,256]
__global__ void k_transpose_pack(const float* __restrict__ W, unsigned* __restrict__ WTw) {
    int i = blockIdx.x * blockDim.x + threadIdx.x;
    if (i >= 256 * 512) return;
    int e = i >> 9, w = i & 511;
    WTw[i] = pk(W[(size_t)(2 * w) * 256 + e], W[(size_t)(2 * w + 1) * 256 + e]);
}

// pack [768,256] fp32 row-major -> [768][128] bf16x2 words
__global__ void k_pack768(const float* __restrict__ Wsrc, unsigned* __restrict__ Wdst) {
    int i = blockIdx.x * blockDim.x + threadIdx.x;
    if (i >= 768 * 128) return;
    int r = i >> 7, w = i & 127;
    Wdst[i] = pk(Wsrc[(size_t)r * 256 + 2 * w], Wsrc[(size_t)r * 256 + 2 * w + 1]);
}

// ---------------- CSR gather (bf16 h) ----------------
__global__ void k_gather(const unsigned* __restrict__ hbf, const int* __restrict__ ss,
                         const int* __restrict__ off, unsigned* __restrict__ Sw, int np) {
    int p = blockIdx.x * 8 + (threadIdx.x >> 5);
    if (p >= np) return;
    int lane = threadIdx.x & 31;
    int beg = __ldg(off + p), end = __ldg(off + p + 1);
    float a0 = 0.f, a1 = 0.f, a2 = 0.f, a3 = 0.f, a4 = 0.f, a5 = 0.f, a6 = 0.f, a7 = 0.f;
    for (int e = beg; e < end; e++) {
        uint4 w = __ldg((const uint4*)(hbf + (size_t)__ldg(ss + e) * 128 + lane * 4));
        float2 f0 = upk(w.x), f1 = upk(w.y), f2 = upk(w.z), f3 = upk(w.w);
        a0 += f0.x; a1 += f0.y; a2 += f1.x; a3 += f1.y;
        a4 += f2.x; a5 += f2.y; a6 += f3.x; a7 += f3.y;
    }
    uint4 o;
    o.x = pk(a0, a1); o.y = pk(a2, a3); o.z = pk(a4, a5); o.w = pk(a6, a7);
    *reinterpret_cast<uint4*>(Sw + (size_t)p * 128 + lane * 4) = o;
}

// ---------------- agg GEMM (k=32 chunks, single-bar 2-stage pipeline) ----------------
// aggw = bf16( Sw[M,1024] @ WTw^T + cnt-weighted bias )
__global__ __launch_bounds__(256) void gemm_agg(
    const unsigned* __restrict__ Aw, const unsigned* __restrict__ Bw,
    unsigned* __restrict__ Cw, int M,
    const float* __restrict__ cnt, const float* __restrict__ bias)
{
    __shared__ unsigned As[2][2048];   // 128 rows x 16 words (64B rows, swizzled)
    __shared__ unsigned Bs[2][2048];
    const int tid = threadIdx.x;
    const int bm = blockIdx.y * 128;
    const int bn = blockIdx.x * 128;

    // staging: thread handles (row, ch) and (row+64, ch); row = tid>>2, ch = tid&3
    const int row = tid >> 2, ch = tid & 3;
    int ar0 = bm + row;       if (ar0 >= M) ar0 = M - 1;   // clamp; garbage rows discarded
    int ar1 = bm + row + 64;  if (ar1 >= M) ar1 = M - 1;
    const unsigned* Ag0 = Aw + (size_t)ar0 * 512 + ch * 4;
    const unsigned* Ag1 = Aw + (size_t)ar1 * 512 + ch * 4;
    const unsigned* Bg0 = Bw + (size_t)(bn + row) * 512 + ch * 4;
    const unsigned* Bg1 = Bw + (size_t)(bn + row + 64) * 512 + ch * 4;

    const unsigned sAb = (unsigned)__cvta_generic_to_shared(&As[0][0]);
    const unsigned sBb = (unsigned)__cvta_generic_to_shared(&Bs[0][0]);
    const unsigned d0 = sw32(row, ch);
    const unsigned d1 = d0 + 4096;     // row+64: same swizzle phase, +64 rows * 64B

    // prologue: chunk 0 -> stage 0
    cp16(sAb + d0, Ag0); cp16(sAb + d1, Ag1);
    cp16(sBb + d0, Bg0); cp16(sBb + d1, Bg1);
    asm volatile("cp.async.commit_group;" ::: "memory");

    const int wid = tid >> 5, lane = tid & 31;
    const int wm = (wid & 1) * 64;
    const int wn = (wid >> 1) * 32;
    const int lrow = (lane & 7) + ((lane >> 3) & 1) * 8;
    const int lc = (lane >> 4) & 1;
    unsigned aoffk[2][4], boffk[2][2];
#pragma unroll
    for (int ks = 0; ks < 2; ks++) {
#pragma unroll
        for (int mi = 0; mi < 4; mi++)
            aoffk[ks][mi] = sw32(wm + mi * 16 + lrow, 2 * ks + lc);
#pragma unroll
        for (int nt = 0; nt < 2; nt++)
            boffk[ks][nt] = sw32(wn + nt * 16 + lrow, 2 * ks + lc);
    }

    float acc[4][4][4];
#pragma unroll
    for (int i = 0; i < 4; i++)
#pragma unroll
        for (int j = 0; j < 4; j++)
#pragma unroll
            for (int q = 0; q < 4; q++) acc[i][j][q] = 0.f;

    for (int c = 0; c < 32; c++) {
        const int buf = c & 1;
        asm volatile("cp.async.wait_group 0;" ::: "memory");
        __syncthreads();
        if (c < 31) {
            const unsigned st = (buf ^ 1) * 8192;
            const int so = (c + 1) * 16;
            cp16(sAb + st + d0, Ag0 + so); cp16(sAb + st + d1, Ag1 + so);
            cp16(sBb + st + d0, Bg0 + so); cp16(sBb + st + d1, Bg1 + so);
            asm volatile("cp.async.commit_group;" ::: "memory");
        }
        const unsigned ab = sAb + buf * 8192;
        const unsigned bb = sBb + buf * 8192;
#pragma unroll
        for (int ks = 0; ks < 2; ks++) {
            unsigned af[4][4], bfr[4][2];
#pragma unroll
            for (int mi = 0; mi < 4; mi++)
                ldsm_x4(af[mi][0], af[mi][1], af[mi][2], af[mi][3], ab + aoffk[ks][mi]);
#pragma unroll
            for (int nt = 0; nt < 2; nt++) {
                unsigned r0, r1, r2, r3;
                ldsm_x4(r0, r1, r2, r3, bb + boffk[ks][nt]);
                bfr[nt * 2 + 0][0] = r0; bfr[nt * 2 + 0][1] = r2;
                bfr[nt * 2 + 1][0] = r1; bfr[nt * 2 + 1][1] = r3;
            }
#pragma unroll
            for (int mi = 0; mi < 4; mi++)
#pragma unroll
                for (int nj = 0; nj < 4; nj++)
                    mma_bf16(acc[mi][nj], af[mi], bfr[nj]);
        }
    }

    // epilogue: +sum_t cnt[m,t]*bias[t,n], pack to bf16x2
    const int eg = lane >> 2, etg = lane & 3;
#pragma unroll
    for (int mi = 0; mi < 4; mi++) {
#pragma unroll
        for (int rr = 0; rr < 2; rr++) {
            int m = bm + wm + mi * 16 + eg + rr * 8;
            if (m >= M) continue;
            float4 c4 = *reinterpret_cast<const float4*>(cnt + (size_t)m * 4);
            unsigned* Cr = Cw + (size_t)m * 128;
#pragma unroll
            for (int nj = 0; nj < 4; nj++) {
                int c = bn + wn + nj * 8 + 2 * etg;
                float add0 = c4.x * __ldg(bias + 0 * 256 + c) + c4.y * __ldg(bias + 1 * 256 + c)
                           + c4.z * __ldg(bias + 2 * 256 + c) + c4.w * __ldg(bias + 3 * 256 + c);
                float add1 = c4.x * __ldg(bias + 0 * 256 + c + 1) + c4.y * __ldg(bias + 1 * 256 + c + 1)
                           + c4.z * __ldg(bias + 2 * 256 + c + 1) + c4.w * __ldg(bias + 3 * 256 + c + 1);
                Cr[c >> 1] = pk(acc[mi][nj][rr * 2 + 0] + add0,
                                acc[mi][nj][rr * 2 + 1] + add1);
            }
        }
    }
}

// ---------------- fused gates GEMM + GRU (single-bar 2-stage pipeline) ----------------
__global__ __launch_bounds__(256) void k_gates(
    const unsigned* __restrict__ aggw, const unsigned* __restrict__ hbfw,
    const float* __restrict__ hin,
    const unsigned* __restrict__ Wihw, const unsigned* __restrict__ Whhw,
    const float* __restrict__ bih, const float* __restrict__ bhh,
    float* __restrict__ hout, unsigned* __restrict__ hbfout, int M)
{
    __shared__ unsigned Aa[2][1024];    // 128 rows x 8 words (32B rows)
    __shared__ unsigned Ah[2][1024];
    __shared__ unsigned Bsx[2][3072];   // 384 rows (6 panels x 64) x 8 words
    const int tid = threadIdx.x;
    const int bm = blockIdx.y * 128;
    const int bn = blockIdx.x * 64;

    // A staging: row = tid>>1, half = tid&1
    const int row = tid >> 1, half = tid & 1;
    int arow = bm + row; if (arow >= M) arow = M - 1;     // garbage rows discarded
    const unsigned* Agp = aggw + (size_t)arow * 128 + half * 4;
    const unsigned* Hgp = hbfw + (size_t)arow * 128 + half * 4;
    const unsigned dAOff = sw_off(row, half);

    // B staging: 3 transfers per thread
    const unsigned* Bgp[3];
    unsigned dBOff[3];
#pragma unroll
    for (int j = 0; j < 3; j++) {
        int idx = j * 256 + tid;
        int R = idx >> 1, hB = idx & 1;
        int p = R >> 6, n = R & 63;
        const unsigned* base = (p < 3) ? (Wihw + (size_t)(p * 256 + bn + n) * 128)
                                       : (Whhw + (size_t)((p - 3) * 256 + bn + n) * 128);
        Bgp[j] = base + hB * 4;
        dBOff[j] = sw_off(R, hB);
    }

    const unsigned sAab = (unsigned)__cvta_generic_to_shared(&Aa[0][0]);
    const unsigned sAhb = (unsigned)__cvta_generic_to_shared(&Ah[0][0]);
    const unsigned sBxb = (unsigned)__cvta_generic_to_shared(&Bsx[0][0]);

    // prologue: chunk 0 -> stage 0
    cp16(sAab + dAOff, Agp);
    cp16(sAhb + dAOff, Hgp);
#pragma unroll
    for (int j = 0; j < 3; j++) cp16(sBxb + dBOff[j], Bgp[j]);
    asm volatile("cp.async.commit_group;" ::: "memory");

    const int wid = tid >> 5, lane = tid & 31;
    const int wm = (wid & 1) * 64;
    const int wn = (wid >> 1) * 16;
    const int lrow = (lane & 7) + ((lane >> 3) & 1) * 8;
    const int lc = (lane >> 4) & 1;
    unsigned aoff[4], bpoff[6];
#pragma unroll
    for (int mi = 0; mi < 4; mi++) aoff[mi] = sw_off(wm + mi * 16 + lrow, lc);
#pragma unroll
    for (int p = 0; p < 6; p++) bpoff[p] = sw_off(p * 64 + wn + lrow, lc);

    float accR[4][2][4], accZ[4][2][4], accI[4][2][4], accH[4][2][4];
#pragma unroll
    for (int i = 0; i < 4; i++)
#pragma unroll
        for (int j = 0; j < 2; j++)
#pragma unroll
            for (int q = 0; q < 4; q++) {
                accR[i][j][q] = 0.f; accZ[i][j][q] = 0.f;
                accI[i][j][q] = 0.f; accH[i][j][q] = 0.f;
            }

    for (int c = 0; c < 16; c++) {
        const int buf = c & 1;
        asm volatile("cp.async.wait_group 0;" ::: "memory");
        __syncthreads();
        if (c < 15) {
            unsigned dA2 = dAOff + (buf ^ 1) * 4096;
            cp16(sAab + dA2, Agp + (c + 1) * 8);
            cp16(sAhb + dA2, Hgp + (c + 1) * 8);
#pragma unroll
            for (int j = 0; j < 3; j++)
                cp16(sBxb + dBOff[j] + (buf ^ 1) * 12288, Bgp[j] + (c + 1) * 8);
            asm volatile("cp.async.commit_group;" ::: "memory");
        }
        const unsigned ab = sAab + buf * 4096;
        const unsigned hb = sAhb + buf * 4096;
        const unsigned bb = sBxb + buf * 12288;
        unsigned afa[4][4], afh[4][4], bfr[6][2][2];
#pragma unroll
        for (int mi = 0; mi < 4; mi++) {
            ldsm_x4(afa[mi][0], afa[mi][1], afa[mi][2], afa[mi][3], ab + aoff[mi]);
            ldsm_x4(afh[mi][0], afh[mi][1], afh[mi][2], afh[mi][3], hb + aoff[mi]);
        }
#pragma unroll
        for (int p = 0; p < 6; p++) {
            unsigned r0, r1, r2, r3;
            ldsm_x4(r0, r1, r2, r3, bb + bpoff[p]);
            bfr[p][0][0] = r0; bfr[p][0][1] = r2;
            bfr[p][1][0] = r1; bfr[p][1][1] = r3;
        }
#pragma unroll
        for (int mi = 0; mi < 4; mi++)
#pragma unroll
            for (int nj = 0; nj < 2; nj++) {
                mma_bf16(accR[mi][nj], afa[mi], bfr[0][nj]);
                mma_bf16(accR[mi][nj], afh[mi], bfr[3][nj]);
                mma_bf16(accZ[mi][nj], afa[mi], bfr[1][nj]);
                mma_bf16(accZ[mi][nj], afh[mi], bfr[4][nj]);
                mma_bf16(accI[mi][nj], afa[mi], bfr[2][nj]);
                mma_bf16(accH[mi][nj], afh[mi], bfr[5][nj]);
            }
    }

    // GRU epilogue
    const int eg = lane >> 2, etg = lane & 3;
    float brz[2][2], bzz[2][2], bin[2][2], bhn[2][2];
#pragma unroll
    for (int nj = 0; nj < 2; nj++)
#pragma unroll
        for (int j = 0; j < 2; j++) {
            int cc = bn + wn + nj * 8 + 2 * etg + j;
            brz[nj][j] = __ldg(bih + cc) + __ldg(bhh + cc);
            bzz[nj][j] = __ldg(bih + 256 + cc) + __ldg(bhh + 256 + cc);
            bin[nj][j] = __ldg(bih + 512 + cc);
            bhn[nj][j] = __ldg(bhh + 512 + cc);
        }

#pragma unroll
    for (int mi = 0; mi < 4; mi++) {
#pragma unroll
        for (int rr = 0; rr < 2; rr++) {
            int m = bm + wm + mi * 16 + eg + rr * 8;
            if (m >= M) continue;
#pragma unroll
            for (int nj = 0; nj < 2; nj++) {
                int c = bn + wn + nj * 8 + 2 * etg;
                float2 hv = *reinterpret_cast<const float2*>(hin + (size_t)m * 256 + c);
                float o01[2];
#pragma unroll
                for (int j = 0; j < 2; j++) {
                    int q = rr * 2 + j;
                    float r = sigm(accR[mi][nj][q] + brz[nj][j]);
                    float z = sigm(accZ[mi][nj][q] + bzz[nj][j]);
                    float gin = accI[mi][nj][q] + bin[nj][j];
                    float ghn = accH[mi][nj][q] + bhn[nj][j];
                    float nn = tanhf(gin + r * ghn);
                    float hj = j ? hv.y : hv.x;
                    o01[j] = (1.f - z) * nn + z * hj;
                }
                *reinterpret_cast<float2*>(hout + (size_t)m * 256 + c) =
                    make_float2(o01[0], o01[1]);
                hbfout[(size_t)m * 128 + (c >> 1)] = pk(o01[0], o01[1]);
            }
        }
    }
}

// ---------------- pooling + classifier ----------------
__global__ void k_pool(const float* __restrict__ h, float* __restrict__ pooled, int M) {
    int c = threadIdx.x;
    int r0 = blockIdx.x * 256;
    int rend = min(r0 + 256, M);
    float s = 0.f;
    for (int r = r0; r < rend; r++) s += h[(size_t)r * 256 + c];
    atomicAdd(&pooled[c], s);
}

__global__ void k_final(const float* __restrict__ pooled, const float* __restrict__ Wc,
                        const float* __restrict__ bc, float* __restrict__ out) {
    __shared__ float red[256];
    int t = threadIdx.x;
    red[t] = pooled[t] * Wc[t];
    __syncthreads();
    for (int s = 128; s > 0; s >>= 1) {
        if (t < s) red[t] += red[t + s];
        __syncthreads();
    }
    if (t == 0) out[0] = 1.f / (1.f + expf(-(red[0] + bc[0])));
}

// ---------------- launch ----------------
extern "C" void kernel_launch(void* const* d_in, const int* in_sizes, int n_in,
                              void* d_out, int out_size) {
    const float* features = (const float*)d_in[0];
    const int* esrc = (const int*)d_in[1];
    const int* edst = (const int*)d_in[2];
    const int* etyp = (const int*)d_in[3];
    const float* W   = (const float*)d_in[4];
    const float* b   = (const float*)d_in[5];
    const float* Wih = (const float*)d_in[6];
    const float* Whh = (const float*)d_in[7];
    const float* bih = (const float*)d_in[8];
    const float* bhh = (const float*)d_in[9];
    const float* Wc  = (const float*)d_in[10];
    const float* bc  = (const float*)d_in[11];
    float* out = (float*)d_out;

    const int M = in_sizes[0] / DIN;   // 50000
    const int E = in_sizes[1];         // 800000
    const int np = M * 4;              // 200000 (dst,type) buckets

    unsigned *Sw, *hbfA, *hbfB, *aggw, *WTw, *Wihw, *Whhw;
    float *hA, *hB, *cnt, *pooled;
    int *icnt, *cur, *off, *bsum, *ss;
    cudaGetSymbolAddress((void**)&Sw, d_Sw);
    cudaGetSymbolAddress((void**)&hA, d_hA);
    cudaGetSymbolAddress((void**)&hB, d_hB);
    cudaGetSymbolAddress((void**)&hbfA, d_hbfA);
    cudaGetSymbolAddress((void**)&hbfB, d_hbfB);
    cudaGetSymbolAddress((void**)&aggw, d_aggw);
    cudaGetSymbolAddress((void**)&cnt, d_cnt);
    cudaGetSymbolAddress((void**)&WTw, d_WTw);
    cudaGetSymbolAddress((void**)&Wihw, d_Wihw);
    cudaGetSymbolAddress((void**)&Whhw, d_Whhw);
    cudaGetSymbolAddress((void**)&pooled, d_pooled);
    cudaGetSymbolAddress((void**)&icnt, d_icnt);
    cudaGetSymbolAddress((void**)&cur, d_cur);
    cudaGetSymbolAddress((void**)&off, d_off);
    cudaGetSymbolAddress((void**)&bsum, d_bsum);
    cudaGetSymbolAddress((void**)&ss, d_ss);

    // ---- one-time (per launch) setup: CSR build + h0 + packed weights ----
    const int nb = (np + 1023) / 1024;
    k_zero<<<(np / 4 + 255) / 256, 256>>>((float4*)icnt, np / 4);
    k_zero<<<(np / 4 + 255) / 256, 256>>>((float4*)cur, np / 4);
    k_count_int<<<(E + 255) / 256, 256>>>(edst, etyp, icnt, E);
    k_cnt2float<<<(np + 255) / 256, 256>>>(icnt, cnt, np);
    k_scan1<<<nb, 256>>>(icnt, off, bsum, np);
    k_scan2<<<1, 256>>>(bsum, nb);
    k_scan3<<<nb, 256>>>(off, bsum, np, E);
    k_place<<<(E + 255) / 256, 256>>>(esrc, edst, etyp, off, cur, ss, E);
    k_init_h<<<((size_t)M * 128 + 255) / 256, 256>>>(features, hA, hbfA, M);
    k_transpose_pack<<<(256 * 512 + 255) / 256, 256>>>(W, WTw);
    k_pack768<<<(768 * 128 + 255) / 256, 256>>>(Wih, Wihw);
    k_pack768<<<(768 * 128 + 255) / 256, 256>>>(Whh, Whhw);

    float* hin = hA;  float* hout = hB;
    unsigned* hbfin = hbfA;  unsigned* hbfout = hbfB;
    const int mb = (M + 127) / 128;
    dim3 gAgg(2, mb), gGates(4, mb);
    const int gGather = (np + 7) / 8;

    for (int step = 0; step < 8; step++) {
        k_gather<<<gGather, 256>>>(hbfin, ss, off, Sw, np);
        gemm_agg<<<gAgg, 256>>>(Sw, WTw, aggw, M, cnt, b);
        k_gates<<<gGates, 256>>>(aggw, hbfin, hin, Wihw, Whhw, bih, bhh, hout, hbfout, M);
        float* t = hin; hin = hout; hout = t;
        unsigned* tw = hbfin; hbfin = hbfout; hbfout = tw;
    }

    k_zero<<<1, 64>>>((float4*)pooled, 64);
    k_pool<<<(M + 255) / 256, 256>>>(hin, pooled, M);
    k_final<<<1, 256>>>(pooled, Wc, bc, out);
}